// round 8
// baseline (speedup 1.0000x reference)
#include <cuda_runtime.h>
#include <cuda_bf16.h>
#include <cstdint>
#include <cstddef>

// Problem constants
#define NW    720
#define LTOK  144
#define DIM   192
#define NHEAD 6
#define HD    32
#define TOW   240
#define SCALE 0.17677669529663687f   // 32^-0.5

// ---------------------------------------------------------------------------
// Scratch
// ---------------------------------------------------------------------------
__device__ float g_qkv[(size_t)NW * 3 * NHEAD * LTOK * HD];  // [w][t][h][l][d]
__device__ float g_bias[(size_t)TOW * NHEAD * LTOK * LTOK];  // [tow*6+h][i*144+j]
__device__ float g_att[(size_t)NW * LTOK * DIM];             // [w][l][h*32+d]

__device__ __forceinline__ int posidx(int a, int b) {
    int za = a / 72, ha = (a % 72) / 12, wa = a % 12;
    int zb = b / 72, hb = (b % 72) / 12, wb = b % 12;
    return 828 * (za + 2 * zb) + 23 * (ha + 6 * hb) + (wa - wb + 11);
}

__device__ __forceinline__ uint32_t smem_u32(const void* p) {
    uint32_t a;
    asm("{ .reg .u64 t; cvta.to.shared.u64 t, %1; cvt.u32.u64 %0, t; }"
        : "=r"(a) : "l"(p));
    return a;
}
__device__ __forceinline__ uint32_t pack2(float a, float b) {
    __nv_bfloat162 t = __floats2bfloat162_rn(a, b);
    return *reinterpret_cast<uint32_t*>(&t);
}
__device__ __forceinline__ void ldsm4(uint32_t* r, uint32_t addr) {
    asm volatile("ldmatrix.sync.aligned.m8n8.x4.shared.b16 {%0,%1,%2,%3}, [%4];"
                 : "=r"(r[0]), "=r"(r[1]), "=r"(r[2]), "=r"(r[3]) : "r"(addr));
}
__device__ __forceinline__ void mma16816(float* d, const uint32_t* a, const uint32_t* b) {
    asm volatile(
        "mma.sync.aligned.m16n8k16.row.col.f32.bf16.bf16.f32 "
        "{%0,%1,%2,%3}, {%4,%5,%6,%7}, {%8,%9}, {%0,%1,%2,%3};"
        : "+f"(d[0]), "+f"(d[1]), "+f"(d[2]), "+f"(d[3])
        : "r"(a[0]), "r"(a[1]), "r"(a[2]), "r"(a[3]), "r"(b[0]), "r"(b[1]));
}

// FFMA-pipe exponential (avoids MUFU). rel err ~3e-8 for |x| < ~80.
__device__ __forceinline__ float exp_fma(float x) {
    float t = x * 1.4426950408889634f;
    float r = rintf(t);
    float f = t - r;
    // 2^f, f in [-0.5, 0.5]: degree-6 Taylor in ln2
    float p = 1.5423875e-4f;
    p = p * f + 1.3333558e-3f;
    p = p * f + 9.6181291e-3f;
    p = p * f + 5.5504109e-2f;
    p = p * f + 2.4022651e-1f;
    p = p * f + 6.9314718e-1f;
    p = p * f + 1.0f;
    int e = (int)r;
    float s = __int_as_float((e + 127) << 23);
    return s * p;
}

// ---------------------------------------------------------------------------
// K0: bias gather/transpose
// ---------------------------------------------------------------------------
__global__ void bias_gather_kernel(const float* __restrict__ table) {
    __shared__ float tile[32][241];
    const int ij0 = blockIdx.x * 32;
    const int tt0 = blockIdx.y * 240;
    const int tid = threadIdx.x;

    for (int e = tid; e < 32 * 240; e += 256) {
        int ii = e / 240, tt = e % 240;
        int ij = ij0 + ii;
        int a = ij / LTOK, b = ij % LTOK;
        tile[ii][tt] = table[(size_t)posidx(a, b) * (TOW * NHEAD) + tt0 + tt];
    }
    __syncthreads();
    for (int e = tid; e < 32 * 240; e += 256) {
        int tt = e / 32, c = e % 32;
        g_bias[(size_t)(tt0 + tt) * (LTOK * LTOK) + ij0 + c] = tile[c][tt];
    }
}

// ---------------------------------------------------------------------------
// HMMA GEMM (exact R7 winner): C[m][n] = sum_k A[m][k]*B[n][k] + bias[n]
// ---------------------------------------------------------------------------
#define ROWB  400
#define AH_OFF 0
#define AL_OFF (64 * ROWB)
#define BH_OFF (2 * 64 * ROWB)
#define BL_OFF (3 * 64 * ROWB)
#define SM_TOTAL (4 * 64 * ROWB)

template <int NT, int MODE>
__global__ __launch_bounds__(128)
void tc_gemm(const float* __restrict__ Ain,
             const float* __restrict__ B,
             const float* __restrict__ bias,
             float* __restrict__ C) {
    extern __shared__ __align__(16) char sm[];
    const uint32_t smb = smem_u32(sm);
    const int tid = threadIdx.x;
    const int wid = tid >> 5, lane = tid & 31;
    const float* A = (MODE == 0) ? g_att : Ain;
    const int m0 = blockIdx.x * 64;

    for (int e = tid; e < 64 * 48; e += 128) {
        int m = e / 48, k4 = e % 48;
        float4 v = *reinterpret_cast<const float4*>(A + (size_t)(m0 + m) * 192 + k4 * 4);
        float hx = __bfloat162float(__float2bfloat16(v.x));
        float hy = __bfloat162float(__float2bfloat16(v.y));
        float hz = __bfloat162float(__float2bfloat16(v.z));
        float hw = __bfloat162float(__float2bfloat16(v.w));
        uint32_t off = m * ROWB + k4 * 8;
        *reinterpret_cast<uint2*>(sm + AH_OFF + off) =
            make_uint2(pack2(hx, hy), pack2(hz, hw));
        *reinterpret_cast<uint2*>(sm + AL_OFF + off) =
            make_uint2(pack2(v.x - hx, v.y - hy), pack2(v.z - hz, v.w - hw));
    }

    const int wm = wid & 1, wn = wid >> 1;
    const int gid = lane >> 2, qid = lane & 3;
    const int g = lane >> 3, r8 = lane & 7;

    for (int nt = 0; nt < NT; nt++) {
        if (nt) __syncthreads();
        for (int e = tid; e < 64 * 48; e += 128) {
            int n = e / 48, k4 = e % 48;
            float4 v = *reinterpret_cast<const float4*>(
                B + (size_t)(nt * 64 + n) * 192 + k4 * 4);
            float hx = __bfloat162float(__float2bfloat16(v.x));
            float hy = __bfloat162float(__float2bfloat16(v.y));
            float hz = __bfloat162float(__float2bfloat16(v.z));
            float hw = __bfloat162float(__float2bfloat16(v.w));
            uint32_t off = n * ROWB + k4 * 8;
            *reinterpret_cast<uint2*>(sm + BH_OFF + off) =
                make_uint2(pack2(hx, hy), pack2(hz, hw));
            *reinterpret_cast<uint2*>(sm + BL_OFF + off) =
                make_uint2(pack2(v.x - hx, v.y - hy), pack2(v.z - hz, v.w - hw));
        }
        __syncthreads();

        float acc[2][4][4];
#pragma unroll
        for (int i = 0; i < 2; i++)
#pragma unroll
            for (int j = 0; j < 4; j++)
#pragma unroll
                for (int c = 0; c < 4; c++) acc[i][j][c] = 0.0f;

#pragma unroll 3
        for (int ks = 0; ks < 12; ks++) {
            const int k0 = ks * 16;
            uint32_t ah[2][4], al[2][4];
#pragma unroll
            for (int mt = 0; mt < 2; mt++) {
                uint32_t row = wm * 32 + mt * 16 + r8 + (g & 1) * 8;
                uint32_t koff = (k0 + (g >> 1) * 8) * 2;
                ldsm4(ah[mt], smb + AH_OFF + row * ROWB + koff);
                ldsm4(al[mt], smb + AL_OFF + row * ROWB + koff);
            }
            uint32_t bh[4][2], bl[4][2];
#pragma unroll
            for (int pr = 0; pr < 2; pr++) {
                uint32_t row = wn * 32 + pr * 16 + r8 + (g >> 1) * 8;
                uint32_t koff = (k0 + (g & 1) * 8) * 2;
                uint32_t th[4], tl[4];
                ldsm4(th, smb + BH_OFF + row * ROWB + koff);
                ldsm4(tl, smb + BL_OFF + row * ROWB + koff);
                bh[pr * 2 + 0][0] = th[0]; bh[pr * 2 + 0][1] = th[1];
                bh[pr * 2 + 1][0] = th[2]; bh[pr * 2 + 1][1] = th[3];
                bl[pr * 2 + 0][0] = tl[0]; bl[pr * 2 + 0][1] = tl[1];
                bl[pr * 2 + 1][0] = tl[2]; bl[pr * 2 + 1][1] = tl[3];
            }
#pragma unroll
            for (int mt = 0; mt < 2; mt++)
#pragma unroll
                for (int ntn = 0; ntn < 4; ntn++) {
                    mma16816(acc[mt][ntn], ah[mt], bh[ntn]);
                    mma16816(acc[mt][ntn], ah[mt], bl[ntn]);
                    mma16816(acc[mt][ntn], al[mt], bh[ntn]);
                }
        }

        const int cbase = nt * 64 + wn * 32;
#pragma unroll
        for (int ntn = 0; ntn < 4; ntn++) {
            const int c = cbase + ntn * 8 + qid * 2;
            const float2 bv = *reinterpret_cast<const float2*>(bias + c);
#pragma unroll
            for (int mt = 0; mt < 2; mt++) {
#pragma unroll
                for (int half = 0; half < 2; half++) {
                    const int m = m0 + wm * 32 + mt * 16 + gid + half * 8;
                    float2 o;
                    o.x = acc[mt][ntn][half * 2 + 0] + bv.x;
                    o.y = acc[mt][ntn][half * 2 + 1] + bv.y;
                    if (MODE == 0) {
                        *reinterpret_cast<float2*>(C + (size_t)m * DIM + c) = o;
                    } else {
                        const int w = m / LTOK, l = m % LTOK;
                        const int t = c / DIM, hh = (c % DIM) / HD, d = c % HD;
                        *reinterpret_cast<float2*>(
                            g_qkv + ((((size_t)w * 3 + t) * NHEAD + hh) * LTOK + l) * HD + d) = o;
                    }
                }
            }
        }
    }
}

// ---------------------------------------------------------------------------
// K2: fused attention (R2 structure; exp on FFMA pipe instead of MUFU).
// ---------------------------------------------------------------------------
__global__ __launch_bounds__(160)
void attn_kernel(const float* __restrict__ mask) {
    __shared__ float4 ks4[LTOK * 8];
    __shared__ float4 vs4[LTOK * 8];

    const int bx = blockIdx.x;
    const int tow = bx / NHEAD;
    const int h = bx % NHEAD;
    const int tid = threadIdx.x;

    for (int wrep = 0; wrep < 3; wrep++) {
        const int w = tow + wrep * TOW;
        const float4* kg = reinterpret_cast<const float4*>(
            g_qkv + (((size_t)w * 3 + 1) * NHEAD + h) * (LTOK * HD));
        const float4* vg = reinterpret_cast<const float4*>(
            g_qkv + (((size_t)w * 3 + 2) * NHEAD + h) * (LTOK * HD));

        __syncthreads();
        for (int e = tid; e < LTOK * 8; e += 160) {
            ks4[e] = kg[e];
            vs4[e] = vg[e];
        }
        __syncthreads();

        if (tid < LTOK) {
            const int i = tid;
            const float4* qg = reinterpret_cast<const float4*>(
                g_qkv + (((size_t)w * 3 + 0) * NHEAD + h) * (LTOK * HD) + i * HD);
            float4 q[8];
#pragma unroll
            for (int d = 0; d < 8; d++) {
                q[d] = qg[d];
                q[d].x *= SCALE; q[d].y *= SCALE; q[d].z *= SCALE; q[d].w *= SCALE;
            }
            const float4* brow = reinterpret_cast<const float4*>(
                g_bias + ((size_t)tow * NHEAD + h) * (LTOK * LTOK) + i * LTOK);
            const float4* mrow = reinterpret_cast<const float4*>(
                mask + ((size_t)w * LTOK + i) * LTOK);

            float4 acc[8];
#pragma unroll
            for (int d = 0; d < 8; d++) acc[d] = make_float4(0.f, 0.f, 0.f, 0.f);
            float lsum = 0.0f;

            for (int j4 = 0; j4 < LTOK / 4; j4++) {
                float4 b4 = brow[j4];
                float4 m4 = mrow[j4];
                float bm[4] = {b4.x + m4.x, b4.y + m4.y, b4.z + m4.z, b4.w + m4.w};
#pragma unroll
                for (int u = 0; u < 4; u++) {
                    const int j = j4 * 4 + u;
                    const float4* kr = &ks4[j * 8];
                    float s0 = 0.f, s1 = 0.f, s2 = 0.f, s3 = 0.f;
#pragma unroll
                    for (int d = 0; d < 8; d += 2) {
                        float4 k0 = kr[d], k1 = kr[d + 1];
                        s0 += q[d].x * k0.x + q[d].y * k0.y;
                        s1 += q[d].z * k0.z + q[d].w * k0.w;
                        s2 += q[d + 1].x * k1.x + q[d + 1].y * k1.y;
                        s3 += q[d + 1].z * k1.z + q[d + 1].w * k1.w;
                    }
                    float p = exp_fma((s0 + s1) + (s2 + s3) + bm[u]);
                    lsum += p;
                    const float4* vr = &vs4[j * 8];
#pragma unroll
                    for (int d = 0; d < 8; d++) {
                        float4 vv = vr[d];
                        acc[d].x += p * vv.x;
                        acc[d].y += p * vv.y;
                        acc[d].z += p * vv.z;
                        acc[d].w += p * vv.w;
                    }
                }
            }
            const float rinv = 1.0f / lsum;
            float4* orow = reinterpret_cast<float4*>(
                g_att + ((size_t)w * LTOK + i) * DIM + h * HD);
#pragma unroll
            for (int d = 0; d < 8; d++) {
                float4 o = acc[d];
                o.x *= rinv; o.y *= rinv; o.z *= rinv; o.w *= rinv;
                orow[d] = o;
            }
        }
    }
}

// ---------------------------------------------------------------------------
// Launch. Inputs: 0 x, 1 mask, 2 w1, 3 b1, 4 w2, 5 b2, 6 bias_table
// ---------------------------------------------------------------------------
extern "C" void kernel_launch(void* const* d_in, const int* in_sizes, int n_in,
                              void* d_out, int out_size) {
    const float* x     = (const float*)d_in[0];
    const float* mask  = (const float*)d_in[1];
    const float* w1    = (const float*)d_in[2];
    const float* b1    = (const float*)d_in[3];
    const float* w2    = (const float*)d_in[4];
    const float* b2    = (const float*)d_in[5];
    const float* table = (const float*)d_in[6];
    float* out = (float*)d_out;

    static bool attr_done = false;
    if (!attr_done) {
        cudaFuncSetAttribute(tc_gemm<9, 1>,
                             cudaFuncAttributeMaxDynamicSharedMemorySize, SM_TOTAL);
        cudaFuncSetAttribute(tc_gemm<3, 0>,
                             cudaFuncAttributeMaxDynamicSharedMemorySize, SM_TOTAL);
        attr_done = true;
    }

    bias_gather_kernel<<<dim3(648, 6), 256>>>(table);
    tc_gemm<9, 1><<<1620, 128, SM_TOTAL>>>(x, w1, b1, nullptr);      // qkv proj
    attn_kernel<<<TOW * NHEAD, 160>>>(mask);
    tc_gemm<3, 0><<<1620, 128, SM_TOTAL>>>(nullptr, w2, b2, out);    // out proj
}

// round 9
// speedup vs baseline: 1.5392x; 1.5392x over previous
#include <cuda_runtime.h>
#include <cuda_bf16.h>
#include <cuda_fp16.h>
#include <cstdint>
#include <cstddef>

// Problem constants
#define NW    720
#define LTOK  144
#define DIM   192
#define NHEAD 6
#define HD    32
#define TOW   240
#define SCALE 0.17677669529663687f   // 32^-0.5

// ---------------------------------------------------------------------------
// Scratch
// ---------------------------------------------------------------------------
__device__ float g_qkv[(size_t)NW * 3 * NHEAD * LTOK * HD];  // [w][t][h][l][d]
__device__ float g_bias[(size_t)TOW * NHEAD * LTOK * LTOK];  // [tow*6+h][i*144+j]
__device__ float g_att[(size_t)NW * LTOK * DIM];             // [w][l][h*32+d]

__device__ __forceinline__ int posidx(int a, int b) {
    int za = a / 72, ha = (a % 72) / 12, wa = a % 12;
    int zb = b / 72, hb = (b % 72) / 12, wb = b % 12;
    return 828 * (za + 2 * zb) + 23 * (ha + 6 * hb) + (wa - wb + 11);
}

__device__ __forceinline__ uint32_t smem_u32(const void* p) {
    uint32_t a;
    asm("{ .reg .u64 t; cvta.to.shared.u64 t, %1; cvt.u32.u64 %0, t; }"
        : "=r"(a) : "l"(p));
    return a;
}
__device__ __forceinline__ uint32_t pack2(float a, float b) {
    __nv_bfloat162 t = __floats2bfloat162_rn(a, b);
    return *reinterpret_cast<uint32_t*>(&t);
}
__device__ __forceinline__ uint32_t packh2(float a, float b) {
    __half2 t = __floats2half2_rn(a, b);
    return *reinterpret_cast<uint32_t*>(&t);
}
__device__ __forceinline__ void ldsm4(uint32_t* r, uint32_t addr) {
    asm volatile("ldmatrix.sync.aligned.m8n8.x4.shared.b16 {%0,%1,%2,%3}, [%4];"
                 : "=r"(r[0]), "=r"(r[1]), "=r"(r[2]), "=r"(r[3]) : "r"(addr));
}
__device__ __forceinline__ void ldsm4t(uint32_t* r, uint32_t addr) {
    asm volatile("ldmatrix.sync.aligned.m8n8.x4.trans.shared.b16 {%0,%1,%2,%3}, [%4];"
                 : "=r"(r[0]), "=r"(r[1]), "=r"(r[2]), "=r"(r[3]) : "r"(addr));
}
__device__ __forceinline__ void mma16816(float* d, const uint32_t* a, const uint32_t* b) {
    asm volatile(
        "mma.sync.aligned.m16n8k16.row.col.f32.bf16.bf16.f32 "
        "{%0,%1,%2,%3}, {%4,%5,%6,%7}, {%8,%9}, {%0,%1,%2,%3};"
        : "+f"(d[0]), "+f"(d[1]), "+f"(d[2]), "+f"(d[3])
        : "r"(a[0]), "r"(a[1]), "r"(a[2]), "r"(a[3]), "r"(b[0]), "r"(b[1]));
}
__device__ __forceinline__ void mma16816h(float* d, const uint32_t* a, const uint32_t* b) {
    asm volatile(
        "mma.sync.aligned.m16n8k16.row.col.f32.f16.f16.f32 "
        "{%0,%1,%2,%3}, {%4,%5,%6,%7}, {%8,%9}, {%0,%1,%2,%3};"
        : "+f"(d[0]), "+f"(d[1]), "+f"(d[2]), "+f"(d[3])
        : "r"(a[0]), "r"(a[1]), "r"(a[2]), "r"(a[3]), "r"(b[0]), "r"(b[1]));
}

// FFMA-pipe exponential. rel err ~3e-8 for moderate |x|.
__device__ __forceinline__ float exp_fma(float x) {
    float t = x * 1.4426950408889634f;
    float r = rintf(t);
    float f = t - r;
    float p = 1.5423875e-4f;
    p = p * f + 1.3333558e-3f;
    p = p * f + 9.6181291e-3f;
    p = p * f + 5.5504109e-2f;
    p = p * f + 2.4022651e-1f;
    p = p * f + 6.9314718e-1f;
    p = p * f + 1.0f;
    int e = (int)r;
    float s = __int_as_float((e + 127) << 23);
    return s * p;
}

// ---------------------------------------------------------------------------
// K0: bias gather/transpose
// ---------------------------------------------------------------------------
__global__ void bias_gather_kernel(const float* __restrict__ table) {
    __shared__ float tile[32][241];
    const int ij0 = blockIdx.x * 32;
    const int tt0 = blockIdx.y * 240;
    const int tid = threadIdx.x;

    for (int e = tid; e < 32 * 240; e += 256) {
        int ii = e / 240, tt = e % 240;
        int ij = ij0 + ii;
        int a = ij / LTOK, b = ij % LTOK;
        tile[ii][tt] = table[(size_t)posidx(a, b) * (TOW * NHEAD) + tt0 + tt];
    }
    __syncthreads();
    for (int e = tid; e < 32 * 240; e += 256) {
        int tt = e / 32, c = e % 32;
        g_bias[(size_t)(tt0 + tt) * (LTOK * LTOK) + ij0 + c] = tile[c][tt];
    }
}

// ---------------------------------------------------------------------------
// HMMA GEMM (exact R7 winner)
// ---------------------------------------------------------------------------
#define ROWB  400
#define AH_OFF 0
#define AL_OFF (64 * ROWB)
#define BH_OFF (2 * 64 * ROWB)
#define BL_OFF (3 * 64 * ROWB)
#define SM_TOTAL (4 * 64 * ROWB)

template <int NT, int MODE>
__global__ __launch_bounds__(128)
void tc_gemm(const float* __restrict__ Ain,
             const float* __restrict__ B,
             const float* __restrict__ bias,
             float* __restrict__ C) {
    extern __shared__ __align__(16) char sm[];
    const uint32_t smb = smem_u32(sm);
    const int tid = threadIdx.x;
    const int wid = tid >> 5, lane = tid & 31;
    const float* A = (MODE == 0) ? g_att : Ain;
    const int m0 = blockIdx.x * 64;

    for (int e = tid; e < 64 * 48; e += 128) {
        int m = e / 48, k4 = e % 48;
        float4 v = *reinterpret_cast<const float4*>(A + (size_t)(m0 + m) * 192 + k4 * 4);
        float hx = __bfloat162float(__float2bfloat16(v.x));
        float hy = __bfloat162float(__float2bfloat16(v.y));
        float hz = __bfloat162float(__float2bfloat16(v.z));
        float hw = __bfloat162float(__float2bfloat16(v.w));
        uint32_t off = m * ROWB + k4 * 8;
        *reinterpret_cast<uint2*>(sm + AH_OFF + off) =
            make_uint2(pack2(hx, hy), pack2(hz, hw));
        *reinterpret_cast<uint2*>(sm + AL_OFF + off) =
            make_uint2(pack2(v.x - hx, v.y - hy), pack2(v.z - hz, v.w - hw));
    }

    const int wm = wid & 1, wn = wid >> 1;
    const int gid = lane >> 2, qid = lane & 3;
    const int g = lane >> 3, r8 = lane & 7;

    for (int nt = 0; nt < NT; nt++) {
        if (nt) __syncthreads();
        for (int e = tid; e < 64 * 48; e += 128) {
            int n = e / 48, k4 = e % 48;
            float4 v = *reinterpret_cast<const float4*>(
                B + (size_t)(nt * 64 + n) * 192 + k4 * 4);
            float hx = __bfloat162float(__float2bfloat16(v.x));
            float hy = __bfloat162float(__float2bfloat16(v.y));
            float hz = __bfloat162float(__float2bfloat16(v.z));
            float hw = __bfloat162float(__float2bfloat16(v.w));
            uint32_t off = n * ROWB + k4 * 8;
            *reinterpret_cast<uint2*>(sm + BH_OFF + off) =
                make_uint2(pack2(hx, hy), pack2(hz, hw));
            *reinterpret_cast<uint2*>(sm + BL_OFF + off) =
                make_uint2(pack2(v.x - hx, v.y - hy), pack2(v.z - hz, v.w - hw));
        }
        __syncthreads();

        float acc[2][4][4];
#pragma unroll
        for (int i = 0; i < 2; i++)
#pragma unroll
            for (int j = 0; j < 4; j++)
#pragma unroll
                for (int c = 0; c < 4; c++) acc[i][j][c] = 0.0f;

#pragma unroll 3
        for (int ks = 0; ks < 12; ks++) {
            const int k0 = ks * 16;
            uint32_t ah[2][4], al[2][4];
#pragma unroll
            for (int mt = 0; mt < 2; mt++) {
                uint32_t row = wm * 32 + mt * 16 + r8 + (g & 1) * 8;
                uint32_t koff = (k0 + (g >> 1) * 8) * 2;
                ldsm4(ah[mt], smb + AH_OFF + row * ROWB + koff);
                ldsm4(al[mt], smb + AL_OFF + row * ROWB + koff);
            }
            uint32_t bh[4][2], bl[4][2];
#pragma unroll
            for (int pr = 0; pr < 2; pr++) {
                uint32_t row = wn * 32 + pr * 16 + r8 + (g >> 1) * 8;
                uint32_t koff = (k0 + (g & 1) * 8) * 2;
                uint32_t th[4], tl[4];
                ldsm4(th, smb + BH_OFF + row * ROWB + koff);
                ldsm4(tl, smb + BL_OFF + row * ROWB + koff);
                bh[pr * 2 + 0][0] = th[0]; bh[pr * 2 + 0][1] = th[1];
                bh[pr * 2 + 1][0] = th[2]; bh[pr * 2 + 1][1] = th[3];
                bl[pr * 2 + 0][0] = tl[0]; bl[pr * 2 + 0][1] = tl[1];
                bl[pr * 2 + 1][0] = tl[2]; bl[pr * 2 + 1][1] = tl[3];
            }
#pragma unroll
            for (int mt = 0; mt < 2; mt++)
#pragma unroll
                for (int ntn = 0; ntn < 4; ntn++) {
                    mma16816(acc[mt][ntn], ah[mt], bh[ntn]);
                    mma16816(acc[mt][ntn], ah[mt], bl[ntn]);
                    mma16816(acc[mt][ntn], al[mt], bh[ntn]);
                }
        }

        const int cbase = nt * 64 + wn * 32;
#pragma unroll
        for (int ntn = 0; ntn < 4; ntn++) {
            const int c = cbase + ntn * 8 + qid * 2;
            const float2 bv = *reinterpret_cast<const float2*>(bias + c);
#pragma unroll
            for (int mt = 0; mt < 2; mt++) {
#pragma unroll
                for (int half = 0; half < 2; half++) {
                    const int m = m0 + wm * 32 + mt * 16 + gid + half * 8;
                    float2 o;
                    o.x = acc[mt][ntn][half * 2 + 0] + bv.x;
                    o.y = acc[mt][ntn][half * 2 + 1] + bv.y;
                    if (MODE == 0) {
                        *reinterpret_cast<float2*>(C + (size_t)m * DIM + c) = o;
                    } else {
                        const int w = m / LTOK, l = m % LTOK;
                        const int t = c / DIM, hh = (c % DIM) / HD, d = c % HD;
                        *reinterpret_cast<float2*>(
                            g_qkv + ((((size_t)w * 3 + t) * NHEAD + hh) * LTOK + l) * HD + d) = o;
                    }
                }
            }
        }
    }
}

// ---------------------------------------------------------------------------
// K2: HMMA fp16 flash-style attention.
// Block = (tow, head), 288 thr = 9 warps; warp r owns Q rows [16r,16r+16).
// Q(scaled)/K/V in fp16 smem, 80B-padded rows (ldmatrix conflict-free).
// Per 16-key chunk: S via 4 f16 mma, add bias+mask (fragment-layout float2
// global reads), exp_fma, repack c-frag -> a-frag, P@V via ldmatrix.trans on V.
// Row sums reduced across the quad with commutative shfl adds (deterministic).
// Single-pass softmax (logits O(0.5); shift-invariant).
// ---------------------------------------------------------------------------
#define AROW 80

__global__ __launch_bounds__(288)
void attn_mma_kernel(const float* __restrict__ mask) {
    __shared__ __align__(16) char sq[LTOK * AROW];
    __shared__ __align__(16) char skk[LTOK * AROW];
    __shared__ __align__(16) char sv[LTOK * AROW];

    const int bx = blockIdx.x;
    const int tow = bx / NHEAD;
    const int h = bx % NHEAD;
    const int tid = threadIdx.x;
    const int warp = tid >> 5, lane = tid & 31;
    const int gid = lane >> 2, qid = lane & 3;
    const int g = lane >> 3, r8 = lane & 7;
    const uint32_t sqb = smem_u32(sq), skb = smem_u32(skk), svb = smem_u32(sv);
    const int r0 = warp * 16;

    const float* bias_base = g_bias + ((size_t)tow * NHEAD + h) * (LTOK * LTOK);
    const float* brow0 = bias_base + (r0 + gid) * LTOK;
    const float* brow1 = bias_base + (r0 + gid + 8) * LTOK;

    for (int wrep = 0; wrep < 3; wrep++) {
        const int w = tow + wrep * TOW;
        const float* qg = g_qkv + (((size_t)w * 3 + 0) * NHEAD + h) * (LTOK * HD);
        const float* kg = g_qkv + (((size_t)w * 3 + 1) * NHEAD + h) * (LTOK * HD);
        const float* vg = g_qkv + (((size_t)w * 3 + 2) * NHEAD + h) * (LTOK * HD);

        __syncthreads();
        // fill fp16 planes: 144 rows x 8 float4 each
        for (int e = tid; e < LTOK * 8; e += 288) {
            int row = e >> 3, d4 = e & 7;
            uint32_t off = row * AROW + d4 * 8;
            float4 a = *reinterpret_cast<const float4*>(qg + row * HD + d4 * 4);
            *reinterpret_cast<uint2*>(sq + off) =
                make_uint2(packh2(a.x * SCALE, a.y * SCALE),
                           packh2(a.z * SCALE, a.w * SCALE));
            float4 b = *reinterpret_cast<const float4*>(kg + row * HD + d4 * 4);
            *reinterpret_cast<uint2*>(skk + off) =
                make_uint2(packh2(b.x, b.y), packh2(b.z, b.w));
            float4 c = *reinterpret_cast<const float4*>(vg + row * HD + d4 * 4);
            *reinterpret_cast<uint2*>(sv + off) =
                make_uint2(packh2(c.x, c.y), packh2(c.z, c.w));
        }
        __syncthreads();

        // Q a-fragments for both k16 steps (held all loop)
        uint32_t aq[2][4];
#pragma unroll
        for (int ks = 0; ks < 2; ks++)
            ldsm4(aq[ks], sqb + (r0 + r8 + (g & 1) * 8) * AROW
                              + (ks * 16 + (g >> 1) * 8) * 2);

        float oacc[4][4];
#pragma unroll
        for (int i = 0; i < 4; i++)
#pragma unroll
            for (int c = 0; c < 4; c++) oacc[i][c] = 0.0f;
        float ls0 = 0.0f, ls1 = 0.0f;

        const float* mrow0 = mask + ((size_t)w * LTOK + r0 + gid) * LTOK;
        const float* mrow1 = mrow0 + 8 * LTOK;

#pragma unroll 3
        for (int nc = 0; nc < 9; nc++) {
            // S = Q @ K^T for keys [16nc, 16nc+16)
            float sacc[2][4] = {{0.f, 0.f, 0.f, 0.f}, {0.f, 0.f, 0.f, 0.f}};
#pragma unroll
            for (int ks = 0; ks < 2; ks++) {
                uint32_t kb[4];
                ldsm4(kb, skb + (nc * 16 + r8 + (g >> 1) * 8) * AROW
                              + (ks * 16 + (g & 1) * 8) * 2);
                mma16816h(sacc[0], aq[ks], kb + 0);
                mma16816h(sacc[1], aq[ks], kb + 2);
            }
            // bias + mask + exp; pack P a-fragments
            uint32_t pa[4];
#pragma unroll
            for (int t2 = 0; t2 < 2; t2++) {
                int col = nc * 16 + t2 * 8 + qid * 2;
                float2 b0 = *reinterpret_cast<const float2*>(brow0 + col);
                float2 m0 = *reinterpret_cast<const float2*>(mrow0 + col);
                float2 b1 = *reinterpret_cast<const float2*>(brow1 + col);
                float2 m1 = *reinterpret_cast<const float2*>(mrow1 + col);
                float p0 = exp_fma(sacc[t2][0] + b0.x + m0.x);
                float p1 = exp_fma(sacc[t2][1] + b0.y + m0.y);
                float p2 = exp_fma(sacc[t2][2] + b1.x + m1.x);
                float p3 = exp_fma(sacc[t2][3] + b1.y + m1.y);
                ls0 += p0 + p1;
                ls1 += p2 + p3;
                pa[2 * t2 + 0] = packh2(p0, p1);
                pa[2 * t2 + 1] = packh2(p2, p3);
            }
            // P @ V
#pragma unroll
            for (int dh = 0; dh < 2; dh++) {
                uint32_t vb[4];
                ldsm4t(vb, svb + (nc * 16 + (g & 1) * 8 + r8) * AROW
                               + (dh * 16 + (g >> 1) * 8) * 2);
                mma16816h(oacc[dh * 2 + 0], pa, vb + 0);
                mma16816h(oacc[dh * 2 + 1], pa, vb + 2);
            }
        }

        // reduce row sums across quad (commutative fp adds -> deterministic)
        ls0 += __shfl_xor_sync(0xFFFFFFFFu, ls0, 1);
        ls0 += __shfl_xor_sync(0xFFFFFFFFu, ls0, 2);
        ls1 += __shfl_xor_sync(0xFFFFFFFFu, ls1, 1);
        ls1 += __shfl_xor_sync(0xFFFFFFFFu, ls1, 2);
        const float ri0 = 1.0f / ls0;
        const float ri1 = 1.0f / ls1;

        float* ob0 = g_att + ((size_t)w * LTOK + r0 + gid) * DIM + h * HD;
        float* ob1 = ob0 + 8 * DIM;
#pragma unroll
        for (int dt = 0; dt < 4; dt++) {
            float2 o0 = make_float2(oacc[dt][0] * ri0, oacc[dt][1] * ri0);
            float2 o1 = make_float2(oacc[dt][2] * ri1, oacc[dt][3] * ri1);
            *reinterpret_cast<float2*>(ob0 + dt * 8 + qid * 2) = o0;
            *reinterpret_cast<float2*>(ob1 + dt * 8 + qid * 2) = o1;
        }
    }
}

// ---------------------------------------------------------------------------
// Launch. Inputs: 0 x, 1 mask, 2 w1, 3 b1, 4 w2, 5 b2, 6 bias_table
// ---------------------------------------------------------------------------
extern "C" void kernel_launch(void* const* d_in, const int* in_sizes, int n_in,
                              void* d_out, int out_size) {
    const float* x     = (const float*)d_in[0];
    const float* mask  = (const float*)d_in[1];
    const float* w1    = (const float*)d_in[2];
    const float* b1    = (const float*)d_in[3];
    const float* w2    = (const float*)d_in[4];
    const float* b2    = (const float*)d_in[5];
    const float* table = (const float*)d_in[6];
    float* out = (float*)d_out;

    static bool attr_done = false;
    if (!attr_done) {
        cudaFuncSetAttribute(tc_gemm<9, 1>,
                             cudaFuncAttributeMaxDynamicSharedMemorySize, SM_TOTAL);
        cudaFuncSetAttribute(tc_gemm<3, 0>,
                             cudaFuncAttributeMaxDynamicSharedMemorySize, SM_TOTAL);
        attr_done = true;
    }

    bias_gather_kernel<<<dim3(648, 6), 256>>>(table);
    tc_gemm<9, 1><<<1620, 128, SM_TOTAL>>>(x, w1, b1, nullptr);      // qkv proj
    attn_mma_kernel<<<TOW * NHEAD, 288>>>(mask);
    tc_gemm<3, 0><<<1620, 128, SM_TOTAL>>>(nullptr, w2, b2, out);    // out proj
}

// round 10
// speedup vs baseline: 1.5407x; 1.0010x over previous
#include <cuda_runtime.h>
#include <cuda_bf16.h>
#include <cuda_fp16.h>
#include <cstdint>
#include <cstddef>

// Problem constants
#define NW    720
#define LTOK  144
#define DIM   192
#define NHEAD 6
#define HD    32
#define TOW   240
#define SCALE 0.17677669529663687f   // 32^-0.5

// ---------------------------------------------------------------------------
// Scratch
// ---------------------------------------------------------------------------
__device__ float g_qkv[(size_t)NW * 3 * NHEAD * LTOK * HD];  // [w][t][h][l][d]
__device__ float g_bias[(size_t)TOW * NHEAD * LTOK * LTOK];  // [tow*6+h][i*144+j]
__device__ float g_att[(size_t)NW * LTOK * DIM];             // [w][l][h*32+d]
__device__ __nv_bfloat16 g_w1h[576 * 192], g_w1l[576 * 192];
__device__ __nv_bfloat16 g_w2h[192 * 192], g_w2l[192 * 192];

__device__ __forceinline__ int posidx(int a, int b) {
    int za = a / 72, ha = (a % 72) / 12, wa = a % 12;
    int zb = b / 72, hb = (b % 72) / 12, wb = b % 12;
    return 828 * (za + 2 * zb) + 23 * (ha + 6 * hb) + (wa - wb + 11);
}

__device__ __forceinline__ uint32_t smem_u32(const void* p) {
    uint32_t a;
    asm("{ .reg .u64 t; cvta.to.shared.u64 t, %1; cvt.u32.u64 %0, t; }"
        : "=r"(a) : "l"(p));
    return a;
}
__device__ __forceinline__ uint32_t pack2(float a, float b) {
    __nv_bfloat162 t = __floats2bfloat162_rn(a, b);
    return *reinterpret_cast<uint32_t*>(&t);
}
__device__ __forceinline__ uint32_t packh2(float a, float b) {
    __half2 t = __floats2half2_rn(a, b);
    return *reinterpret_cast<uint32_t*>(&t);
}
__device__ __forceinline__ void ldsm4(uint32_t* r, uint32_t addr) {
    asm volatile("ldmatrix.sync.aligned.m8n8.x4.shared.b16 {%0,%1,%2,%3}, [%4];"
                 : "=r"(r[0]), "=r"(r[1]), "=r"(r[2]), "=r"(r[3]) : "r"(addr));
}
__device__ __forceinline__ void ldsm4t(uint32_t* r, uint32_t addr) {
    asm volatile("ldmatrix.sync.aligned.m8n8.x4.trans.shared.b16 {%0,%1,%2,%3}, [%4];"
                 : "=r"(r[0]), "=r"(r[1]), "=r"(r[2]), "=r"(r[3]) : "r"(addr));
}
__device__ __forceinline__ void mma16816(float* d, const uint32_t* a, const uint32_t* b) {
    asm volatile(
        "mma.sync.aligned.m16n8k16.row.col.f32.bf16.bf16.f32 "
        "{%0,%1,%2,%3}, {%4,%5,%6,%7}, {%8,%9}, {%0,%1,%2,%3};"
        : "+f"(d[0]), "+f"(d[1]), "+f"(d[2]), "+f"(d[3])
        : "r"(a[0]), "r"(a[1]), "r"(a[2]), "r"(a[3]), "r"(b[0]), "r"(b[1]));
}
__device__ __forceinline__ void mma16816h(float* d, const uint32_t* a, const uint32_t* b) {
    asm volatile(
        "mma.sync.aligned.m16n8k16.row.col.f32.f16.f16.f32 "
        "{%0,%1,%2,%3}, {%4,%5,%6,%7}, {%8,%9}, {%0,%1,%2,%3};"
        : "+f"(d[0]), "+f"(d[1]), "+f"(d[2]), "+f"(d[3])
        : "r"(a[0]), "r"(a[1]), "r"(a[2]), "r"(a[3]), "r"(b[0]), "r"(b[1]));
}

// FFMA-pipe exponential. rel err ~3e-8 for moderate |x|.
__device__ __forceinline__ float exp_fma(float x) {
    float t = x * 1.4426950408889634f;
    float r = rintf(t);
    float f = t - r;
    float p = 1.5423875e-4f;
    p = p * f + 1.3333558e-3f;
    p = p * f + 9.6181291e-3f;
    p = p * f + 5.5504109e-2f;
    p = p * f + 2.4022651e-1f;
    p = p * f + 6.9314718e-1f;
    p = p * f + 1.0f;
    int e = (int)r;
    float s = __int_as_float((e + 127) << 23);
    return s * p;
}

// ---------------------------------------------------------------------------
// K-1: weight split prep (w1 576 rows, w2 192 rows -> bf16 hi/lo planes)
// ---------------------------------------------------------------------------
__global__ void wsplit_kernel(const float* __restrict__ w1,
                              const float* __restrict__ w2) {
    const int row = blockIdx.x, col = threadIdx.x;
    float v;
    __nv_bfloat16 *hd, *ld;
    if (row < 576) {
        v = w1[row * 192 + col];
        hd = g_w1h + row * 192 + col;
        ld = g_w1l + row * 192 + col;
    } else {
        int r = row - 576;
        v = w2[r * 192 + col];
        hd = g_w2h + r * 192 + col;
        ld = g_w2l + r * 192 + col;
    }
    __nv_bfloat16 h = __float2bfloat16(v);
    *hd = h;
    *ld = __float2bfloat16(v - __bfloat162float(h));
}

// ---------------------------------------------------------------------------
// K0: bias gather/transpose
// ---------------------------------------------------------------------------
__global__ void bias_gather_kernel(const float* __restrict__ table) {
    __shared__ float tile[32][241];
    const int ij0 = blockIdx.x * 32;
    const int tt0 = blockIdx.y * 240;
    const int tid = threadIdx.x;

    for (int e = tid; e < 32 * 240; e += 256) {
        int ii = e / 240, tt = e % 240;
        int ij = ij0 + ii;
        int a = ij / LTOK, b = ij % LTOK;
        tile[ii][tt] = table[(size_t)posidx(a, b) * (TOW * NHEAD) + tt0 + tt];
    }
    __syncthreads();
    for (int e = tid; e < 32 * 240; e += 256) {
        int tt = e / 32, c = e % 32;
        g_bias[(size_t)(tt0 + tt) * (LTOK * LTOK) + ij0 + c] = tile[c][tt];
    }
}

// ---------------------------------------------------------------------------
// HMMA GEMM: C[m][n] = sum_k A[m][k]*B[n][k] + bias[n]
// 256 thr (8 warps: 4 m-subtiles x 2 n-subtiles of 32x32), BM=128, BN=64.
// A: fp32 -> bf16 hi/lo split in smem (once). B: precomputed bf16 hi/lo
// planes (g_w1*/g_w2* by MODE), pure vector-copy fill per N-tile.
// 3-term split product AhBh + AhBl + AlBh, fp32 acc.
// ---------------------------------------------------------------------------
#define ROWB  400
#define AH_OFF 0
#define AL_OFF (128 * ROWB)                  // 51200
#define BH_OFF (2 * 128 * ROWB)              // 102400
#define BL_OFF (BH_OFF + 64 * ROWB)          // 128000
#define SM_TOTAL (BL_OFF + 64 * ROWB)        // 153600

template <int NT, int MODE>
__global__ __launch_bounds__(256)
void tc_gemm(const float* __restrict__ Ain,
             const float* __restrict__ bias,
             float* __restrict__ C) {
    extern __shared__ __align__(16) char sm[];
    const uint32_t smb = smem_u32(sm);
    const int tid = threadIdx.x;
    const int wid = tid >> 5, lane = tid & 31;
    const float* A = (MODE == 0) ? g_att : Ain;
    const __nv_bfloat16* Bh = (MODE == 0) ? g_w2h : g_w1h;
    const __nv_bfloat16* Bl = (MODE == 0) ? g_w2l : g_w1l;
    const int m0 = blockIdx.x * 128;

    // ---- A fill (once): 128 x 192 f32 -> bf16 hi/lo planes ----
    for (int e = tid; e < 128 * 48; e += 256) {
        int m = e / 48, k4 = e % 48;
        float4 v = *reinterpret_cast<const float4*>(A + (size_t)(m0 + m) * 192 + k4 * 4);
        float hx = __bfloat162float(__float2bfloat16(v.x));
        float hy = __bfloat162float(__float2bfloat16(v.y));
        float hz = __bfloat162float(__float2bfloat16(v.z));
        float hw = __bfloat162float(__float2bfloat16(v.w));
        uint32_t off = m * ROWB + k4 * 8;
        *reinterpret_cast<uint2*>(sm + AH_OFF + off) =
            make_uint2(pack2(hx, hy), pack2(hz, hw));
        *reinterpret_cast<uint2*>(sm + AL_OFF + off) =
            make_uint2(pack2(v.x - hx, v.y - hy), pack2(v.z - hz, v.w - hw));
    }

    const int wm = wid & 3, wn = wid >> 2;       // 4x2 warp grid
    const int gid = lane >> 2, qid = lane & 3;
    const int g = lane >> 3, r8 = lane & 7;

    for (int nt = 0; nt < NT; nt++) {
        if (nt) __syncthreads();
        // ---- B tile fill: 64 rows x 24 uint4 per plane (bf16 copies) ----
        for (int e = tid; e < 64 * 24; e += 256) {
            int n = e / 24, c = e % 24;
            uint32_t off = n * ROWB + c * 16;
            *reinterpret_cast<uint4*>(sm + BH_OFF + off) =
                *reinterpret_cast<const uint4*>(Bh + (size_t)(nt * 64 + n) * 192 + c * 8);
            *reinterpret_cast<uint4*>(sm + BL_OFF + off) =
                *reinterpret_cast<const uint4*>(Bl + (size_t)(nt * 64 + n) * 192 + c * 8);
        }
        __syncthreads();

        float acc[2][4][4];
#pragma unroll
        for (int i = 0; i < 2; i++)
#pragma unroll
            for (int j = 0; j < 4; j++)
#pragma unroll
                for (int c = 0; c < 4; c++) acc[i][j][c] = 0.0f;

#pragma unroll 3
        for (int ks = 0; ks < 12; ks++) {
            const int k0 = ks * 16;
            uint32_t ah[2][4], al[2][4];
#pragma unroll
            for (int mt = 0; mt < 2; mt++) {
                uint32_t row = wm * 32 + mt * 16 + r8 + (g & 1) * 8;
                uint32_t koff = (k0 + (g >> 1) * 8) * 2;
                ldsm4(ah[mt], smb + AH_OFF + row * ROWB + koff);
                ldsm4(al[mt], smb + AL_OFF + row * ROWB + koff);
            }
            uint32_t bh[4][2], bl[4][2];
#pragma unroll
            for (int pr = 0; pr < 2; pr++) {
                uint32_t row = wn * 32 + pr * 16 + r8 + (g >> 1) * 8;
                uint32_t koff = (k0 + (g & 1) * 8) * 2;
                uint32_t th[4], tl[4];
                ldsm4(th, smb + BH_OFF + row * ROWB + koff);
                ldsm4(tl, smb + BL_OFF + row * ROWB + koff);
                bh[pr * 2 + 0][0] = th[0]; bh[pr * 2 + 0][1] = th[1];
                bh[pr * 2 + 1][0] = th[2]; bh[pr * 2 + 1][1] = th[3];
                bl[pr * 2 + 0][0] = tl[0]; bl[pr * 2 + 0][1] = tl[1];
                bl[pr * 2 + 1][0] = tl[2]; bl[pr * 2 + 1][1] = tl[3];
            }
#pragma unroll
            for (int mt = 0; mt < 2; mt++)
#pragma unroll
                for (int ntn = 0; ntn < 4; ntn++) {
                    mma16816(acc[mt][ntn], ah[mt], bh[ntn]);
                    mma16816(acc[mt][ntn], ah[mt], bl[ntn]);
                    mma16816(acc[mt][ntn], al[mt], bh[ntn]);
                }
        }

        const int cbase = nt * 64 + wn * 32;
#pragma unroll
        for (int ntn = 0; ntn < 4; ntn++) {
            const int c = cbase + ntn * 8 + qid * 2;
            const float2 bv = *reinterpret_cast<const float2*>(bias + c);
#pragma unroll
            for (int mt = 0; mt < 2; mt++) {
#pragma unroll
                for (int half = 0; half < 2; half++) {
                    const int m = m0 + wm * 32 + mt * 16 + gid + half * 8;
                    float2 o;
                    o.x = acc[mt][ntn][half * 2 + 0] + bv.x;
                    o.y = acc[mt][ntn][half * 2 + 1] + bv.y;
                    if (MODE == 0) {
                        *reinterpret_cast<float2*>(C + (size_t)m * DIM + c) = o;
                    } else {
                        const int w = m / LTOK, l = m % LTOK;
                        const int t = c / DIM, hh = (c % DIM) / HD, d = c % HD;
                        *reinterpret_cast<float2*>(
                            g_qkv + ((((size_t)w * 3 + t) * NHEAD + hh) * LTOK + l) * HD + d) = o;
                    }
                }
            }
        }
    }
}

// ---------------------------------------------------------------------------
// K2: HMMA fp16 flash-style attention (exact R9 winner).
// ---------------------------------------------------------------------------
#define AROW 80

__global__ __launch_bounds__(288)
void attn_mma_kernel(const float* __restrict__ mask) {
    __shared__ __align__(16) char sq[LTOK * AROW];
    __shared__ __align__(16) char skk[LTOK * AROW];
    __shared__ __align__(16) char sv[LTOK * AROW];

    const int bx = blockIdx.x;
    const int tow = bx / NHEAD;
    const int h = bx % NHEAD;
    const int tid = threadIdx.x;
    const int warp = tid >> 5, lane = tid & 31;
    const int gid = lane >> 2, qid = lane & 3;
    const int g = lane >> 3, r8 = lane & 7;
    const uint32_t sqb = smem_u32(sq), skb = smem_u32(skk), svb = smem_u32(sv);
    const int r0 = warp * 16;

    const float* bias_base = g_bias + ((size_t)tow * NHEAD + h) * (LTOK * LTOK);
    const float* brow0 = bias_base + (r0 + gid) * LTOK;
    const float* brow1 = bias_base + (r0 + gid + 8) * LTOK;

    for (int wrep = 0; wrep < 3; wrep++) {
        const int w = tow + wrep * TOW;
        const float* qg = g_qkv + (((size_t)w * 3 + 0) * NHEAD + h) * (LTOK * HD);
        const float* kg = g_qkv + (((size_t)w * 3 + 1) * NHEAD + h) * (LTOK * HD);
        const float* vg = g_qkv + (((size_t)w * 3 + 2) * NHEAD + h) * (LTOK * HD);

        __syncthreads();
        for (int e = tid; e < LTOK * 8; e += 288) {
            int row = e >> 3, d4 = e & 7;
            uint32_t off = row * AROW + d4 * 8;
            float4 a = *reinterpret_cast<const float4*>(qg + row * HD + d4 * 4);
            *reinterpret_cast<uint2*>(sq + off) =
                make_uint2(packh2(a.x * SCALE, a.y * SCALE),
                           packh2(a.z * SCALE, a.w * SCALE));
            float4 b = *reinterpret_cast<const float4*>(kg + row * HD + d4 * 4);
            *reinterpret_cast<uint2*>(skk + off) =
                make_uint2(packh2(b.x, b.y), packh2(b.z, b.w));
            float4 c = *reinterpret_cast<const float4*>(vg + row * HD + d4 * 4);
            *reinterpret_cast<uint2*>(sv + off) =
                make_uint2(packh2(c.x, c.y), packh2(c.z, c.w));
        }
        __syncthreads();

        uint32_t aq[2][4];
#pragma unroll
        for (int ks = 0; ks < 2; ks++)
            ldsm4(aq[ks], sqb + (r0 + r8 + (g & 1) * 8) * AROW
                              + (ks * 16 + (g >> 1) * 8) * 2);

        float oacc[4][4];
#pragma unroll
        for (int i = 0; i < 4; i++)
#pragma unroll
            for (int c = 0; c < 4; c++) oacc[i][c] = 0.0f;
        float ls0 = 0.0f, ls1 = 0.0f;

        const float* mrow0 = mask + ((size_t)w * LTOK + r0 + gid) * LTOK;
        const float* mrow1 = mrow0 + 8 * LTOK;

#pragma unroll 3
        for (int nc = 0; nc < 9; nc++) {
            float sacc[2][4] = {{0.f, 0.f, 0.f, 0.f}, {0.f, 0.f, 0.f, 0.f}};
#pragma unroll
            for (int ks = 0; ks < 2; ks++) {
                uint32_t kb[4];
                ldsm4(kb, skb + (nc * 16 + r8 + (g >> 1) * 8) * AROW
                              + (ks * 16 + (g & 1) * 8) * 2);
                mma16816h(sacc[0], aq[ks], kb + 0);
                mma16816h(sacc[1], aq[ks], kb + 2);
            }
            uint32_t pa[4];
#pragma unroll
            for (int t2 = 0; t2 < 2; t2++) {
                int col = nc * 16 + t2 * 8 + qid * 2;
                float2 b0 = *reinterpret_cast<const float2*>(brow0 + col);
                float2 m0 = *reinterpret_cast<const float2*>(mrow0 + col);
                float2 b1 = *reinterpret_cast<const float2*>(brow1 + col);
                float2 m1 = *reinterpret_cast<const float2*>(mrow1 + col);
                float p0 = exp_fma(sacc[t2][0] + b0.x + m0.x);
                float p1 = exp_fma(sacc[t2][1] + b0.y + m0.y);
                float p2 = exp_fma(sacc[t2][2] + b1.x + m1.x);
                float p3 = exp_fma(sacc[t2][3] + b1.y + m1.y);
                ls0 += p0 + p1;
                ls1 += p2 + p3;
                pa[2 * t2 + 0] = packh2(p0, p1);
                pa[2 * t2 + 1] = packh2(p2, p3);
            }
#pragma unroll
            for (int dh = 0; dh < 2; dh++) {
                uint32_t vb[4];
                ldsm4t(vb, svb + (nc * 16 + (g & 1) * 8 + r8) * AROW
                               + (dh * 16 + (g >> 1) * 8) * 2);
                mma16816h(oacc[dh * 2 + 0], pa, vb + 0);
                mma16816h(oacc[dh * 2 + 1], pa, vb + 2);
            }
        }

        ls0 += __shfl_xor_sync(0xFFFFFFFFu, ls0, 1);
        ls0 += __shfl_xor_sync(0xFFFFFFFFu, ls0, 2);
        ls1 += __shfl_xor_sync(0xFFFFFFFFu, ls1, 1);
        ls1 += __shfl_xor_sync(0xFFFFFFFFu, ls1, 2);
        const float ri0 = 1.0f / ls0;
        const float ri1 = 1.0f / ls1;

        float* ob0 = g_att + ((size_t)w * LTOK + r0 + gid) * DIM + h * HD;
        float* ob1 = ob0 + 8 * DIM;
#pragma unroll
        for (int dt = 0; dt < 4; dt++) {
            float2 o0 = make_float2(oacc[dt][0] * ri0, oacc[dt][1] * ri0);
            float2 o1 = make_float2(oacc[dt][2] * ri1, oacc[dt][3] * ri1);
            *reinterpret_cast<float2*>(ob0 + dt * 8 + qid * 2) = o0;
            *reinterpret_cast<float2*>(ob1 + dt * 8 + qid * 2) = o1;
        }
    }
}

// ---------------------------------------------------------------------------
// Launch. Inputs: 0 x, 1 mask, 2 w1, 3 b1, 4 w2, 5 b2, 6 bias_table
// ---------------------------------------------------------------------------
extern "C" void kernel_launch(void* const* d_in, const int* in_sizes, int n_in,
                              void* d_out, int out_size) {
    const float* x     = (const float*)d_in[0];
    const float* mask  = (const float*)d_in[1];
    const float* w1    = (const float*)d_in[2];
    const float* b1    = (const float*)d_in[3];
    const float* w2    = (const float*)d_in[4];
    const float* b2    = (const float*)d_in[5];
    const float* table = (const float*)d_in[6];
    float* out = (float*)d_out;

    static bool attr_done = false;
    if (!attr_done) {
        cudaFuncSetAttribute(tc_gemm<9, 1>,
                             cudaFuncAttributeMaxDynamicSharedMemorySize, SM_TOTAL);
        cudaFuncSetAttribute(tc_gemm<3, 0>,
                             cudaFuncAttributeMaxDynamicSharedMemorySize, SM_TOTAL);
        attr_done = true;
    }

    wsplit_kernel<<<768, 192>>>(w1, w2);
    bias_gather_kernel<<<dim3(648, 6), 256>>>(table);
    tc_gemm<9, 1><<<810, 256, SM_TOTAL>>>(x, b1, nullptr);        // qkv proj
    attn_mma_kernel<<<TOW * NHEAD, 288>>>(mask);
    tc_gemm<3, 0><<<810, 256, SM_TOTAL>>>(nullptr, b2, out);      // out proj
}

// round 11
// speedup vs baseline: 1.5506x; 1.0064x over previous
#include <cuda_runtime.h>
#include <cuda_bf16.h>
#include <cuda_fp16.h>
#include <cstdint>
#include <cstddef>

// Problem constants
#define NW    720
#define LTOK  144
#define DIM   192
#define NHEAD 6
#define HD    32
#define TOW   240
#define SCALE 0.17677669529663687f   // 32^-0.5

// ---------------------------------------------------------------------------
// Scratch
// ---------------------------------------------------------------------------
__device__ __half g_qkv[(size_t)NW * 3 * NHEAD * LTOK * HD];  // fp16 [w][t][h][l][d]
__device__ float g_bias[(size_t)TOW * NHEAD * LTOK * LTOK];   // [tow*6+h][i*144+j]
__device__ float g_att[(size_t)NW * LTOK * DIM];              // [w][l][h*32+d]
__device__ __nv_bfloat16 g_w1h[576 * 192], g_w1l[576 * 192];  // Q rows pre-scaled
__device__ __nv_bfloat16 g_w2h[192 * 192], g_w2l[192 * 192];

__device__ __forceinline__ int posidx(int a, int b) {
    int za = a / 72, ha = (a % 72) / 12, wa = a % 12;
    int zb = b / 72, hb = (b % 72) / 12, wb = b % 12;
    return 828 * (za + 2 * zb) + 23 * (ha + 6 * hb) + (wa - wb + 11);
}

__device__ __forceinline__ uint32_t smem_u32(const void* p) {
    uint32_t a;
    asm("{ .reg .u64 t; cvta.to.shared.u64 t, %1; cvt.u32.u64 %0, t; }"
        : "=r"(a) : "l"(p));
    return a;
}
__device__ __forceinline__ uint32_t pack2(float a, float b) {
    __nv_bfloat162 t = __floats2bfloat162_rn(a, b);
    return *reinterpret_cast<uint32_t*>(&t);
}
__device__ __forceinline__ uint32_t packh2(float a, float b) {
    __half2 t = __floats2half2_rn(a, b);
    return *reinterpret_cast<uint32_t*>(&t);
}
__device__ __forceinline__ void ldsm4(uint32_t* r, uint32_t addr) {
    asm volatile("ldmatrix.sync.aligned.m8n8.x4.shared.b16 {%0,%1,%2,%3}, [%4];"
                 : "=r"(r[0]), "=r"(r[1]), "=r"(r[2]), "=r"(r[3]) : "r"(addr));
}
__device__ __forceinline__ void ldsm4t(uint32_t* r, uint32_t addr) {
    asm volatile("ldmatrix.sync.aligned.m8n8.x4.trans.shared.b16 {%0,%1,%2,%3}, [%4];"
                 : "=r"(r[0]), "=r"(r[1]), "=r"(r[2]), "=r"(r[3]) : "r"(addr));
}
__device__ __forceinline__ void mma16816(float* d, const uint32_t* a, const uint32_t* b) {
    asm volatile(
        "mma.sync.aligned.m16n8k16.row.col.f32.bf16.bf16.f32 "
        "{%0,%1,%2,%3}, {%4,%5,%6,%7}, {%8,%9}, {%0,%1,%2,%3};"
        : "+f"(d[0]), "+f"(d[1]), "+f"(d[2]), "+f"(d[3])
        : "r"(a[0]), "r"(a[1]), "r"(a[2]), "r"(a[3]), "r"(b[0]), "r"(b[1]));
}
__device__ __forceinline__ void mma16816h(float* d, const uint32_t* a, const uint32_t* b) {
    asm volatile(
        "mma.sync.aligned.m16n8k16.row.col.f32.f16.f16.f32 "
        "{%0,%1,%2,%3}, {%4,%5,%6,%7}, {%8,%9}, {%0,%1,%2,%3};"
        : "+f"(d[0]), "+f"(d[1]), "+f"(d[2]), "+f"(d[3])
        : "r"(a[0]), "r"(a[1]), "r"(a[2]), "r"(a[3]), "r"(b[0]), "r"(b[1]));
}

// FFMA-pipe exponential. rel err ~3e-8 for moderate |x|.
__device__ __forceinline__ float exp_fma(float x) {
    float t = x * 1.4426950408889634f;
    float r = rintf(t);
    float f = t - r;
    float p = 1.5423875e-4f;
    p = p * f + 1.3333558e-3f;
    p = p * f + 9.6181291e-3f;
    p = p * f + 5.5504109e-2f;
    p = p * f + 2.4022651e-1f;
    p = p * f + 6.9314718e-1f;
    p = p * f + 1.0f;
    int e = (int)r;
    float s = __int_as_float((e + 127) << 23);
    return s * p;
}

// ---------------------------------------------------------------------------
// K-1: weight split prep. Q-rows of w1 (n<192) pre-scaled by SCALE.
// ---------------------------------------------------------------------------
__global__ void wsplit_kernel(const float* __restrict__ w1,
                              const float* __restrict__ w2) {
    const int row = blockIdx.x, col = threadIdx.x;
    float v;
    __nv_bfloat16 *hd, *ld;
    if (row < 576) {
        v = w1[row * 192 + col];
        if (row < 192) v *= SCALE;
        hd = g_w1h + row * 192 + col;
        ld = g_w1l + row * 192 + col;
    } else {
        int r = row - 576;
        v = w2[r * 192 + col];
        hd = g_w2h + r * 192 + col;
        ld = g_w2l + r * 192 + col;
    }
    __nv_bfloat16 h = __float2bfloat16(v);
    *hd = h;
    *ld = __float2bfloat16(v - __bfloat162float(h));
}

// ---------------------------------------------------------------------------
// K0: bias gather/transpose
// ---------------------------------------------------------------------------
__global__ void bias_gather_kernel(const float* __restrict__ table) {
    __shared__ float tile[32][241];
    const int ij0 = blockIdx.x * 32;
    const int tt0 = blockIdx.y * 240;
    const int tid = threadIdx.x;

    for (int e = tid; e < 32 * 240; e += 256) {
        int ii = e / 240, tt = e % 240;
        int ij = ij0 + ii;
        int a = ij / LTOK, b = ij % LTOK;
        tile[ii][tt] = table[(size_t)posidx(a, b) * (TOW * NHEAD) + tt0 + tt];
    }
    __syncthreads();
    for (int e = tid; e < 32 * 240; e += 256) {
        int tt = e / 32, c = e % 32;
        g_bias[(size_t)(tt0 + tt) * (LTOK * LTOK) + ij0 + c] = tile[c][tt];
    }
}

// ---------------------------------------------------------------------------
// HMMA GEMM: 256 thr, BM=128, BN=64; A bf16 hi/lo split in smem (once);
// B from precomputed bf16 planes (vector copy). MODE 1: fp16 store to g_qkv
// with SCALE-folded bias on Q cols. MODE 0: fp32 row-major C.
// ---------------------------------------------------------------------------
#define ROWB  400
#define AH_OFF 0
#define AL_OFF (128 * ROWB)
#define BH_OFF (2 * 128 * ROWB)
#define BL_OFF (BH_OFF + 64 * ROWB)
#define SM_TOTAL (BL_OFF + 64 * ROWB)

template <int NT, int MODE>
__global__ __launch_bounds__(256)
void tc_gemm(const float* __restrict__ Ain,
             const float* __restrict__ bias,
             float* __restrict__ C) {
    extern __shared__ __align__(16) char sm[];
    const uint32_t smb = smem_u32(sm);
    const int tid = threadIdx.x;
    const int wid = tid >> 5, lane = tid & 31;
    const float* A = (MODE == 0) ? g_att : Ain;
    const __nv_bfloat16* Bh = (MODE == 0) ? g_w2h : g_w1h;
    const __nv_bfloat16* Bl = (MODE == 0) ? g_w2l : g_w1l;
    const int m0 = blockIdx.x * 128;

    for (int e = tid; e < 128 * 48; e += 256) {
        int m = e / 48, k4 = e % 48;
        float4 v = *reinterpret_cast<const float4*>(A + (size_t)(m0 + m) * 192 + k4 * 4);
        float hx = __bfloat162float(__float2bfloat16(v.x));
        float hy = __bfloat162float(__float2bfloat16(v.y));
        float hz = __bfloat162float(__float2bfloat16(v.z));
        float hw = __bfloat162float(__float2bfloat16(v.w));
        uint32_t off = m * ROWB + k4 * 8;
        *reinterpret_cast<uint2*>(sm + AH_OFF + off) =
            make_uint2(pack2(hx, hy), pack2(hz, hw));
        *reinterpret_cast<uint2*>(sm + AL_OFF + off) =
            make_uint2(pack2(v.x - hx, v.y - hy), pack2(v.z - hz, v.w - hw));
    }

    const int wm = wid & 3, wn = wid >> 2;
    const int gid = lane >> 2, qid = lane & 3;
    const int g = lane >> 3, r8 = lane & 7;

    for (int nt = 0; nt < NT; nt++) {
        if (nt) __syncthreads();
        for (int e = tid; e < 64 * 24; e += 256) {
            int n = e / 24, c = e % 24;
            uint32_t off = n * ROWB + c * 16;
            *reinterpret_cast<uint4*>(sm + BH_OFF + off) =
                *reinterpret_cast<const uint4*>(Bh + (size_t)(nt * 64 + n) * 192 + c * 8);
            *reinterpret_cast<uint4*>(sm + BL_OFF + off) =
                *reinterpret_cast<const uint4*>(Bl + (size_t)(nt * 64 + n) * 192 + c * 8);
        }
        __syncthreads();

        float acc[2][4][4];
#pragma unroll
        for (int i = 0; i < 2; i++)
#pragma unroll
            for (int j = 0; j < 4; j++)
#pragma unroll
                for (int c = 0; c < 4; c++) acc[i][j][c] = 0.0f;

#pragma unroll 3
        for (int ks = 0; ks < 12; ks++) {
            const int k0 = ks * 16;
            uint32_t ah[2][4], al[2][4];
#pragma unroll
            for (int mt = 0; mt < 2; mt++) {
                uint32_t row = wm * 32 + mt * 16 + r8 + (g & 1) * 8;
                uint32_t koff = (k0 + (g >> 1) * 8) * 2;
                ldsm4(ah[mt], smb + AH_OFF + row * ROWB + koff);
                ldsm4(al[mt], smb + AL_OFF + row * ROWB + koff);
            }
            uint32_t bh[4][2], bl[4][2];
#pragma unroll
            for (int pr = 0; pr < 2; pr++) {
                uint32_t row = wn * 32 + pr * 16 + r8 + (g >> 1) * 8;
                uint32_t koff = (k0 + (g & 1) * 8) * 2;
                uint32_t th[4], tl[4];
                ldsm4(th, smb + BH_OFF + row * ROWB + koff);
                ldsm4(tl, smb + BL_OFF + row * ROWB + koff);
                bh[pr * 2 + 0][0] = th[0]; bh[pr * 2 + 0][1] = th[1];
                bh[pr * 2 + 1][0] = th[2]; bh[pr * 2 + 1][1] = th[3];
                bl[pr * 2 + 0][0] = tl[0]; bl[pr * 2 + 0][1] = tl[1];
                bl[pr * 2 + 1][0] = tl[2]; bl[pr * 2 + 1][1] = tl[3];
            }
#pragma unroll
            for (int mt = 0; mt < 2; mt++)
#pragma unroll
                for (int ntn = 0; ntn < 4; ntn++) {
                    mma16816(acc[mt][ntn], ah[mt], bh[ntn]);
                    mma16816(acc[mt][ntn], ah[mt], bl[ntn]);
                    mma16816(acc[mt][ntn], al[mt], bh[ntn]);
                }
        }

        const int cbase = nt * 64 + wn * 32;
#pragma unroll
        for (int ntn = 0; ntn < 4; ntn++) {
            const int c = cbase + ntn * 8 + qid * 2;
            float2 bv = *reinterpret_cast<const float2*>(bias + c);
            if (MODE == 1 && c < 192) { bv.x *= SCALE; bv.y *= SCALE; }
#pragma unroll
            for (int mt = 0; mt < 2; mt++) {
#pragma unroll
                for (int half = 0; half < 2; half++) {
                    const int m = m0 + wm * 32 + mt * 16 + gid + half * 8;
                    float ox = acc[mt][ntn][half * 2 + 0] + bv.x;
                    float oy = acc[mt][ntn][half * 2 + 1] + bv.y;
                    if (MODE == 0) {
                        *reinterpret_cast<float2*>(C + (size_t)m * DIM + c) =
                            make_float2(ox, oy);
                    } else {
                        const int w = m / LTOK, l = m % LTOK;
                        const int t = c / DIM, hh = (c % DIM) / HD, d = c % HD;
                        *reinterpret_cast<uint32_t*>(
                            g_qkv + ((((size_t)w * 3 + t) * NHEAD + hh) * LTOK + l) * HD + d)
                            = packh2(ox, oy);
                    }
                }
            }
        }
    }
}

// ---------------------------------------------------------------------------
// K2: HMMA fp16 attention. g_qkv already fp16 & Q pre-scaled -> fills are
// pure uint4 copies. Bias matrix cached in smem as fp16 once per block
// (stride 152 halves: conflict-free fragment reads), reused across 3 windows.
// ---------------------------------------------------------------------------
#define AROW 80
#define SQ_OFF 0
#define SK_OFF (LTOK * AROW)
#define SV_OFF (2 * LTOK * AROW)
#define SB_OFF (3 * LTOK * AROW)              // 34560
#define SBSTRIDE 152
#define ATTN_SMEM (SB_OFF + LTOK * SBSTRIDE * 2)   // 34560 + 43776 = 78336

__global__ __launch_bounds__(288)
void attn_mma_kernel(const float* __restrict__ mask) {
    extern __shared__ __align__(16) char sm[];
    const int bx = blockIdx.x;
    const int tow = bx / NHEAD;
    const int h = bx % NHEAD;
    const int tid = threadIdx.x;
    const int warp = tid >> 5, lane = tid & 31;
    const int gid = lane >> 2, qid = lane & 3;
    const int g = lane >> 3, r8 = lane & 7;
    const uint32_t smb = smem_u32(sm);
    const int r0 = warp * 16;

    // ---- bias -> smem fp16 (once per block) ----
    const float* bias_base = g_bias + ((size_t)tow * NHEAD + h) * (LTOK * LTOK);
    for (int e = tid; e < LTOK * 72; e += 288) {
        int row = e / 72, c2 = e % 72;
        float2 v = *reinterpret_cast<const float2*>(bias_base + row * LTOK + c2 * 2);
        *reinterpret_cast<uint32_t*>(sm + SB_OFF + (row * SBSTRIDE + c2 * 2) * 2) =
            packh2(v.x, v.y);
    }

    const __half* sb0 = reinterpret_cast<const __half*>(sm + SB_OFF) + (r0 + gid) * SBSTRIDE;
    const __half* sb1 = sb0 + 8 * SBSTRIDE;

    for (int wrep = 0; wrep < 3; wrep++) {
        const int w = tow + wrep * TOW;
        const __half* qg = g_qkv + (((size_t)w * 3 + 0) * NHEAD + h) * (LTOK * HD);
        const __half* kg = g_qkv + (((size_t)w * 3 + 1) * NHEAD + h) * (LTOK * HD);
        const __half* vg = g_qkv + (((size_t)w * 3 + 2) * NHEAD + h) * (LTOK * HD);

        __syncthreads();
        // qkv fills: pure 16B copies (row = 32 halves = 4 x uint4)
        for (int e = tid; e < LTOK * 4; e += 288) {
            int row = e >> 2, c4 = e & 3;
            uint32_t off = row * AROW + c4 * 16;
            *reinterpret_cast<uint4*>(sm + SQ_OFF + off) =
                *reinterpret_cast<const uint4*>(qg + row * HD + c4 * 8);
            *reinterpret_cast<uint4*>(sm + SK_OFF + off) =
                *reinterpret_cast<const uint4*>(kg + row * HD + c4 * 8);
            *reinterpret_cast<uint4*>(sm + SV_OFF + off) =
                *reinterpret_cast<const uint4*>(vg + row * HD + c4 * 8);
        }
        __syncthreads();

        uint32_t aq[2][4];
#pragma unroll
        for (int ks = 0; ks < 2; ks++)
            ldsm4(aq[ks], smb + SQ_OFF + (r0 + r8 + (g & 1) * 8) * AROW
                              + (ks * 16 + (g >> 1) * 8) * 2);

        float oacc[4][4];
#pragma unroll
        for (int i = 0; i < 4; i++)
#pragma unroll
            for (int c = 0; c < 4; c++) oacc[i][c] = 0.0f;
        float ls0 = 0.0f, ls1 = 0.0f;

        const float* mrow0 = mask + ((size_t)w * LTOK + r0 + gid) * LTOK;
        const float* mrow1 = mrow0 + 8 * LTOK;

#pragma unroll 3
        for (int nc = 0; nc < 9; nc++) {
            float sacc[2][4] = {{0.f, 0.f, 0.f, 0.f}, {0.f, 0.f, 0.f, 0.f}};
#pragma unroll
            for (int ks = 0; ks < 2; ks++) {
                uint32_t kb[4];
                ldsm4(kb, smb + SK_OFF + (nc * 16 + r8 + (g >> 1) * 8) * AROW
                              + (ks * 16 + (g & 1) * 8) * 2);
                mma16816h(sacc[0], aq[ks], kb + 0);
                mma16816h(sacc[1], aq[ks], kb + 2);
            }
            uint32_t pa[4];
#pragma unroll
            for (int t2 = 0; t2 < 2; t2++) {
                int col = nc * 16 + t2 * 8 + qid * 2;
                float2 b0 = __half22float2(*reinterpret_cast<const __half2*>(sb0 + col));
                float2 b1 = __half22float2(*reinterpret_cast<const __half2*>(sb1 + col));
                float2 m0 = *reinterpret_cast<const float2*>(mrow0 + col);
                float2 m1 = *reinterpret_cast<const float2*>(mrow1 + col);
                float p0 = exp_fma(sacc[t2][0] + b0.x + m0.x);
                float p1 = exp_fma(sacc[t2][1] + b0.y + m0.y);
                float p2 = exp_fma(sacc[t2][2] + b1.x + m1.x);
                float p3 = exp_fma(sacc[t2][3] + b1.y + m1.y);
                ls0 += p0 + p1;
                ls1 += p2 + p3;
                pa[2 * t2 + 0] = packh2(p0, p1);
                pa[2 * t2 + 1] = packh2(p2, p3);
            }
#pragma unroll
            for (int dh = 0; dh < 2; dh++) {
                uint32_t vb[4];
                ldsm4t(vb, smb + SV_OFF + (nc * 16 + (g & 1) * 8 + r8) * AROW
                               + (dh * 16 + (g >> 1) * 8) * 2);
                mma16816h(oacc[dh * 2 + 0], pa, vb + 0);
                mma16816h(oacc[dh * 2 + 1], pa, vb + 2);
            }
        }

        ls0 += __shfl_xor_sync(0xFFFFFFFFu, ls0, 1);
        ls0 += __shfl_xor_sync(0xFFFFFFFFu, ls0, 2);
        ls1 += __shfl_xor_sync(0xFFFFFFFFu, ls1, 1);
        ls1 += __shfl_xor_sync(0xFFFFFFFFu, ls1, 2);
        const float ri0 = 1.0f / ls0;
        const float ri1 = 1.0f / ls1;

        float* ob0 = g_att + ((size_t)w * LTOK + r0 + gid) * DIM + h * HD;
        float* ob1 = ob0 + 8 * DIM;
#pragma unroll
        for (int dt = 0; dt < 4; dt++) {
            float2 o0 = make_float2(oacc[dt][0] * ri0, oacc[dt][1] * ri0);
            float2 o1 = make_float2(oacc[dt][2] * ri1, oacc[dt][3] * ri1);
            *reinterpret_cast<float2*>(ob0 + dt * 8 + qid * 2) = o0;
            *reinterpret_cast<float2*>(ob1 + dt * 8 + qid * 2) = o1;
        }
    }
}

// ---------------------------------------------------------------------------
// Launch. Inputs: 0 x, 1 mask, 2 w1, 3 b1, 4 w2, 5 b2, 6 bias_table
// ---------------------------------------------------------------------------
extern "C" void kernel_launch(void* const* d_in, const int* in_sizes, int n_in,
                              void* d_out, int out_size) {
    const float* x     = (const float*)d_in[0];
    const float* mask  = (const float*)d_in[1];
    const float* w1    = (const float*)d_in[2];
    const float* b1    = (const float*)d_in[3];
    const float* w2    = (const float*)d_in[4];
    const float* b2    = (const float*)d_in[5];
    const float* table = (const float*)d_in[6];
    float* out = (float*)d_out;

    static bool attr_done = false;
    if (!attr_done) {
        cudaFuncSetAttribute(tc_gemm<9, 1>,
                             cudaFuncAttributeMaxDynamicSharedMemorySize, SM_TOTAL);
        cudaFuncSetAttribute(tc_gemm<3, 0>,
                             cudaFuncAttributeMaxDynamicSharedMemorySize, SM_TOTAL);
        cudaFuncSetAttribute(attn_mma_kernel,
                             cudaFuncAttributeMaxDynamicSharedMemorySize, ATTN_SMEM);
        attr_done = true;
    }

    wsplit_kernel<<<768, 192>>>(w1, w2);
    bias_gather_kernel<<<dim3(648, 6), 256>>>(table);
    tc_gemm<9, 1><<<810, 256, SM_TOTAL>>>(x, b1, nullptr);        // qkv proj
    attn_mma_kernel<<<TOW * NHEAD, 288, ATTN_SMEM>>>(mask);
    tc_gemm<3, 0><<<810, 256, SM_TOTAL>>>(nullptr, b2, out);      // out proj
}

// round 12
// speedup vs baseline: 1.7865x; 1.1522x over previous
#include <cuda_runtime.h>
#include <cuda_bf16.h>
#include <cuda_fp16.h>
#include <cstdint>
#include <cstddef>

// Problem constants
#define NW    720
#define LTOK  144
#define DIM   192
#define NHEAD 6
#define HD    32
#define TOW   240
#define SCALE 0.17677669529663687f   // 32^-0.5

// ---------------------------------------------------------------------------
// Scratch
// ---------------------------------------------------------------------------
__device__ __half g_qkv[(size_t)NW * 3 * NHEAD * LTOK * HD];  // fp16 [w][t][h][l][d]
__device__ float g_bias[(size_t)TOW * NHEAD * LTOK * LTOK];   // [tow*6+h][i*144+j]
__device__ __half g_att[(size_t)NW * LTOK * DIM];             // fp16 [w][l][h*32+d]
__device__ __nv_bfloat16 g_w1h[576 * 192], g_w1l[576 * 192];  // Q rows pre-scaled
__device__ __half g_w2h[192 * 192], g_w2l[192 * 192];         // fp16 planes

__device__ __forceinline__ int posidx(int a, int b) {
    int za = a / 72, ha = (a % 72) / 12, wa = a % 12;
    int zb = b / 72, hb = (b % 72) / 12, wb = b % 12;
    return 828 * (za + 2 * zb) + 23 * (ha + 6 * hb) + (wa - wb + 11);
}

__device__ __forceinline__ uint32_t smem_u32(const void* p) {
    uint32_t a;
    asm("{ .reg .u64 t; cvta.to.shared.u64 t, %1; cvt.u32.u64 %0, t; }"
        : "=r"(a) : "l"(p));
    return a;
}
__device__ __forceinline__ uint32_t pack2(float a, float b) {
    __nv_bfloat162 t = __floats2bfloat162_rn(a, b);
    return *reinterpret_cast<uint32_t*>(&t);
}
__device__ __forceinline__ uint32_t packh2(float a, float b) {
    __half2 t = __floats2half2_rn(a, b);
    return *reinterpret_cast<uint32_t*>(&t);
}
__device__ __forceinline__ void ldsm4(uint32_t* r, uint32_t addr) {
    asm volatile("ldmatrix.sync.aligned.m8n8.x4.shared.b16 {%0,%1,%2,%3}, [%4];"
                 : "=r"(r[0]), "=r"(r[1]), "=r"(r[2]), "=r"(r[3]) : "r"(addr));
}
__device__ __forceinline__ void ldsm4t(uint32_t* r, uint32_t addr) {
    asm volatile("ldmatrix.sync.aligned.m8n8.x4.trans.shared.b16 {%0,%1,%2,%3}, [%4];"
                 : "=r"(r[0]), "=r"(r[1]), "=r"(r[2]), "=r"(r[3]) : "r"(addr));
}
__device__ __forceinline__ void mma16816(float* d, const uint32_t* a, const uint32_t* b) {
    asm volatile(
        "mma.sync.aligned.m16n8k16.row.col.f32.bf16.bf16.f32 "
        "{%0,%1,%2,%3}, {%4,%5,%6,%7}, {%8,%9}, {%0,%1,%2,%3};"
        : "+f"(d[0]), "+f"(d[1]), "+f"(d[2]), "+f"(d[3])
        : "r"(a[0]), "r"(a[1]), "r"(a[2]), "r"(a[3]), "r"(b[0]), "r"(b[1]));
}
__device__ __forceinline__ void mma16816h(float* d, const uint32_t* a, const uint32_t* b) {
    asm volatile(
        "mma.sync.aligned.m16n8k16.row.col.f32.f16.f16.f32 "
        "{%0,%1,%2,%3}, {%4,%5,%6,%7}, {%8,%9}, {%0,%1,%2,%3};"
        : "+f"(d[0]), "+f"(d[1]), "+f"(d[2]), "+f"(d[3])
        : "r"(a[0]), "r"(a[1]), "r"(a[2]), "r"(a[3]), "r"(b[0]), "r"(b[1]));
}

// FFMA-pipe exponential. rel err ~3e-8 for moderate |x|.
__device__ __forceinline__ float exp_fma(float x) {
    float t = x * 1.4426950408889634f;
    float r = rintf(t);
    float f = t - r;
    float p = 1.5423875e-4f;
    p = p * f + 1.3333558e-3f;
    p = p * f + 9.6181291e-3f;
    p = p * f + 5.5504109e-2f;
    p = p * f + 2.4022651e-1f;
    p = p * f + 6.9314718e-1f;
    p = p * f + 1.0f;
    int e = (int)r;
    float s = __int_as_float((e + 127) << 23);
    return s * p;
}

// ---------------------------------------------------------------------------
// K-1: weight split prep. w1 -> bf16 hi/lo (Q-rows pre-scaled). w2 -> fp16 hi/lo.
// ---------------------------------------------------------------------------
__global__ void wsplit_kernel(const float* __restrict__ w1,
                              const float* __restrict__ w2) {
    const int row = blockIdx.x, col = threadIdx.x;
    if (row < 576) {
        float v = w1[row * 192 + col];
        if (row < 192) v *= SCALE;
        __nv_bfloat16 h = __float2bfloat16(v);
        g_w1h[row * 192 + col] = h;
        g_w1l[row * 192 + col] = __float2bfloat16(v - __bfloat162float(h));
    } else {
        int r = row - 576;
        float v = w2[r * 192 + col];
        __half h = __float2half(v);
        g_w2h[r * 192 + col] = h;
        g_w2l[r * 192 + col] = __float2half(v - __half2float(h));
    }
}

// ---------------------------------------------------------------------------
// K0: bias gather/transpose
// ---------------------------------------------------------------------------
__global__ void bias_gather_kernel(const float* __restrict__ table) {
    __shared__ float tile[32][241];
    const int ij0 = blockIdx.x * 32;
    const int tt0 = blockIdx.y * 240;
    const int tid = threadIdx.x;

    for (int e = tid; e < 32 * 240; e += 256) {
        int ii = e / 240, tt = e % 240;
        int ij = ij0 + ii;
        int a = ij / LTOK, b = ij % LTOK;
        tile[ii][tt] = table[(size_t)posidx(a, b) * (TOW * NHEAD) + tt0 + tt];
    }
    __syncthreads();
    for (int e = tid; e < 32 * 240; e += 256) {
        int tt = e / 32, c = e % 32;
        g_bias[(size_t)(tt0 + tt) * (LTOK * LTOK) + ij0 + c] = tile[c][tt];
    }
}

// ---------------------------------------------------------------------------
// K1: qkv GEMM (R9 geometry: 128 thr, BM=64, grid 1620, 2 CTA/SM).
// A = x fp32 -> bf16 hi/lo split in smem; B = precomputed bf16 planes (copy).
// 3-term split AhBh + AhBl + AlBh, fp32 acc. fp16 store to g_qkv.
// ---------------------------------------------------------------------------
#define ROWB  400
#define AH_OFF 0
#define AL_OFF (64 * ROWB)
#define BH_OFF (2 * 64 * ROWB)
#define BL_OFF (3 * 64 * ROWB)
#define QKV_SMEM (4 * 64 * ROWB)        // 102400

__global__ __launch_bounds__(128)
void tc_gemm_qkv(const float* __restrict__ x, const float* __restrict__ bias) {
    extern __shared__ __align__(16) char sm[];
    const uint32_t smb = smem_u32(sm);
    const int tid = threadIdx.x;
    const int wid = tid >> 5, lane = tid & 31;
    const int m0 = blockIdx.x * 64;

    for (int e = tid; e < 64 * 48; e += 128) {
        int m = e / 48, k4 = e % 48;
        float4 v = *reinterpret_cast<const float4*>(x + (size_t)(m0 + m) * 192 + k4 * 4);
        float hx = __bfloat162float(__float2bfloat16(v.x));
        float hy = __bfloat162float(__float2bfloat16(v.y));
        float hz = __bfloat162float(__float2bfloat16(v.z));
        float hw = __bfloat162float(__float2bfloat16(v.w));
        uint32_t off = m * ROWB + k4 * 8;
        *reinterpret_cast<uint2*>(sm + AH_OFF + off) =
            make_uint2(pack2(hx, hy), pack2(hz, hw));
        *reinterpret_cast<uint2*>(sm + AL_OFF + off) =
            make_uint2(pack2(v.x - hx, v.y - hy), pack2(v.z - hz, v.w - hw));
    }

    const int wm = wid & 1, wn = wid >> 1;
    const int gid = lane >> 2, qid = lane & 3;
    const int g = lane >> 3, r8 = lane & 7;

    for (int nt = 0; nt < 9; nt++) {
        if (nt) __syncthreads();
        for (int e = tid; e < 64 * 24; e += 128) {
            int n = e / 24, c = e % 24;
            uint32_t off = n * ROWB + c * 16;
            *reinterpret_cast<uint4*>(sm + BH_OFF + off) =
                *reinterpret_cast<const uint4*>(g_w1h + (size_t)(nt * 64 + n) * 192 + c * 8);
            *reinterpret_cast<uint4*>(sm + BL_OFF + off) =
                *reinterpret_cast<const uint4*>(g_w1l + (size_t)(nt * 64 + n) * 192 + c * 8);
        }
        __syncthreads();

        float acc[2][4][4];
#pragma unroll
        for (int i = 0; i < 2; i++)
#pragma unroll
            for (int j = 0; j < 4; j++)
#pragma unroll
                for (int c = 0; c < 4; c++) acc[i][j][c] = 0.0f;

#pragma unroll 3
        for (int ks = 0; ks < 12; ks++) {
            const int k0 = ks * 16;
            uint32_t ah[2][4], al[2][4];
#pragma unroll
            for (int mt = 0; mt < 2; mt++) {
                uint32_t row = wm * 32 + mt * 16 + r8 + (g & 1) * 8;
                uint32_t koff = (k0 + (g >> 1) * 8) * 2;
                ldsm4(ah[mt], smb + AH_OFF + row * ROWB + koff);
                ldsm4(al[mt], smb + AL_OFF + row * ROWB + koff);
            }
            uint32_t bh[4][2], bl[4][2];
#pragma unroll
            for (int pr = 0; pr < 2; pr++) {
                uint32_t row = wn * 32 + pr * 16 + r8 + (g >> 1) * 8;
                uint32_t koff = (k0 + (g & 1) * 8) * 2;
                uint32_t th[4], tl[4];
                ldsm4(th, smb + BH_OFF + row * ROWB + koff);
                ldsm4(tl, smb + BL_OFF + row * ROWB + koff);
                bh[pr * 2 + 0][0] = th[0]; bh[pr * 2 + 0][1] = th[1];
                bh[pr * 2 + 1][0] = th[2]; bh[pr * 2 + 1][1] = th[3];
                bl[pr * 2 + 0][0] = tl[0]; bl[pr * 2 + 0][1] = tl[1];
                bl[pr * 2 + 1][0] = tl[2]; bl[pr * 2 + 1][1] = tl[3];
            }
#pragma unroll
            for (int mt = 0; mt < 2; mt++)
#pragma unroll
                for (int ntn = 0; ntn < 4; ntn++) {
                    mma16816(acc[mt][ntn], ah[mt], bh[ntn]);
                    mma16816(acc[mt][ntn], ah[mt], bl[ntn]);
                    mma16816(acc[mt][ntn], al[mt], bh[ntn]);
                }
        }

        const int cbase = nt * 64 + wn * 32;
#pragma unroll
        for (int ntn = 0; ntn < 4; ntn++) {
            const int c = cbase + ntn * 8 + qid * 2;
            float2 bv = *reinterpret_cast<const float2*>(bias + c);
            if (c < 192) { bv.x *= SCALE; bv.y *= SCALE; }
            const int t = c / DIM, hh = (c % DIM) / HD, d = c % HD;
#pragma unroll
            for (int mt = 0; mt < 2; mt++) {
#pragma unroll
                for (int half = 0; half < 2; half++) {
                    const int m = m0 + wm * 32 + mt * 16 + gid + half * 8;
                    const int w = m / LTOK, l = m % LTOK;
                    *reinterpret_cast<uint32_t*>(
                        g_qkv + ((((size_t)w * 3 + t) * NHEAD + hh) * LTOK + l) * HD + d)
                        = packh2(acc[mt][ntn][half * 2 + 0] + bv.x,
                                 acc[mt][ntn][half * 2 + 1] + bv.y);
                }
            }
        }
    }
}

// ---------------------------------------------------------------------------
// K3: out-proj GEMM, fp16 2-term. A = g_att fp16 (exact, single plane);
// B = w2 fp16 hi/lo. C = A*Bh + A*Bl. 128 thr, BM=64, grid 1620.
// ---------------------------------------------------------------------------
#define OA_OFF 0
#define OBH_OFF (64 * ROWB)
#define OBL_OFF (2 * 64 * ROWB)
#define OUT_SMEM (3 * 64 * ROWB)        // 76800

__global__ __launch_bounds__(128)
void tc_gemm_out(const float* __restrict__ bias, float* __restrict__ C) {
    extern __shared__ __align__(16) char sm[];
    const uint32_t smb = smem_u32(sm);
    const int tid = threadIdx.x;
    const int wid = tid >> 5, lane = tid & 31;
    const int m0 = blockIdx.x * 64;

    // A fill: pure fp16 copies (64 rows x 24 uint4)
    for (int e = tid; e < 64 * 24; e += 128) {
        int m = e / 24, c4 = e % 24;
        *reinterpret_cast<uint4*>(sm + OA_OFF + m * ROWB + c4 * 16) =
            *reinterpret_cast<const uint4*>(g_att + (size_t)(m0 + m) * 192 + c4 * 8);
    }

    const int wm = wid & 1, wn = wid >> 1;
    const int gid = lane >> 2, qid = lane & 3;
    const int g = lane >> 3, r8 = lane & 7;

    for (int nt = 0; nt < 3; nt++) {
        if (nt) __syncthreads();
        for (int e = tid; e < 64 * 24; e += 128) {
            int n = e / 24, c = e % 24;
            uint32_t off = n * ROWB + c * 16;
            *reinterpret_cast<uint4*>(sm + OBH_OFF + off) =
                *reinterpret_cast<const uint4*>(g_w2h + (size_t)(nt * 64 + n) * 192 + c * 8);
            *reinterpret_cast<uint4*>(sm + OBL_OFF + off) =
                *reinterpret_cast<const uint4*>(g_w2l + (size_t)(nt * 64 + n) * 192 + c * 8);
        }
        __syncthreads();

        float acc[2][4][4];
#pragma unroll
        for (int i = 0; i < 2; i++)
#pragma unroll
            for (int j = 0; j < 4; j++)
#pragma unroll
                for (int c = 0; c < 4; c++) acc[i][j][c] = 0.0f;

#pragma unroll 3
        for (int ks = 0; ks < 12; ks++) {
            const int k0 = ks * 16;
            uint32_t aa[2][4];
#pragma unroll
            for (int mt = 0; mt < 2; mt++) {
                uint32_t row = wm * 32 + mt * 16 + r8 + (g & 1) * 8;
                uint32_t koff = (k0 + (g >> 1) * 8) * 2;
                ldsm4(aa[mt], smb + OA_OFF + row * ROWB + koff);
            }
            uint32_t bh[4][2], bl[4][2];
#pragma unroll
            for (int pr = 0; pr < 2; pr++) {
                uint32_t row = wn * 32 + pr * 16 + r8 + (g >> 1) * 8;
                uint32_t koff = (k0 + (g & 1) * 8) * 2;
                uint32_t th[4], tl[4];
                ldsm4(th, smb + OBH_OFF + row * ROWB + koff);
                ldsm4(tl, smb + OBL_OFF + row * ROWB + koff);
                bh[pr * 2 + 0][0] = th[0]; bh[pr * 2 + 0][1] = th[1];
                bh[pr * 2 + 1][0] = th[2]; bh[pr * 2 + 1][1] = th[3];
                bl[pr * 2 + 0][0] = tl[0]; bl[pr * 2 + 0][1] = tl[1];
                bl[pr * 2 + 1][0] = tl[2]; bl[pr * 2 + 1][1] = tl[3];
            }
#pragma unroll
            for (int mt = 0; mt < 2; mt++)
#pragma unroll
                for (int ntn = 0; ntn < 4; ntn++) {
                    mma16816h(acc[mt][ntn], aa[mt], bh[ntn]);
                    mma16816h(acc[mt][ntn], aa[mt], bl[ntn]);
                }
        }

        const int cbase = nt * 64 + wn * 32;
#pragma unroll
        for (int ntn = 0; ntn < 4; ntn++) {
            const int c = cbase + ntn * 8 + qid * 2;
            const float2 bv = *reinterpret_cast<const float2*>(bias + c);
#pragma unroll
            for (int mt = 0; mt < 2; mt++) {
#pragma unroll
                for (int half = 0; half < 2; half++) {
                    const int m = m0 + wm * 32 + mt * 16 + gid + half * 8;
                    *reinterpret_cast<float2*>(C + (size_t)m * DIM + c) =
                        make_float2(acc[mt][ntn][half * 2 + 0] + bv.x,
                                    acc[mt][ntn][half * 2 + 1] + bv.y);
                }
            }
        }
    }
}

// ---------------------------------------------------------------------------
// K2: HMMA fp16 attention (R11 winner; g_att store now fp16).
// ---------------------------------------------------------------------------
#define AROW 80
#define SQ_OFF 0
#define SK_OFF (LTOK * AROW)
#define SV_OFF (2 * LTOK * AROW)
#define SB_OFF (3 * LTOK * AROW)
#define SBSTRIDE 152
#define ATTN_SMEM (SB_OFF + LTOK * SBSTRIDE * 2)

__global__ __launch_bounds__(288)
void attn_mma_kernel(const float* __restrict__ mask) {
    extern __shared__ __align__(16) char sm[];
    const int bx = blockIdx.x;
    const int tow = bx / NHEAD;
    const int h = bx % NHEAD;
    const int tid = threadIdx.x;
    const int warp = tid >> 5, lane = tid & 31;
    const int gid = lane >> 2, qid = lane & 3;
    const int g = lane >> 3, r8 = lane & 7;
    const uint32_t smb = smem_u32(sm);
    const int r0 = warp * 16;

    const float* bias_base = g_bias + ((size_t)tow * NHEAD + h) * (LTOK * LTOK);
    for (int e = tid; e < LTOK * 72; e += 288) {
        int row = e / 72, c2 = e % 72;
        float2 v = *reinterpret_cast<const float2*>(bias_base + row * LTOK + c2 * 2);
        *reinterpret_cast<uint32_t*>(sm + SB_OFF + (row * SBSTRIDE + c2 * 2) * 2) =
            packh2(v.x, v.y);
    }

    const __half* sb0 = reinterpret_cast<const __half*>(sm + SB_OFF) + (r0 + gid) * SBSTRIDE;
    const __half* sb1 = sb0 + 8 * SBSTRIDE;

    for (int wrep = 0; wrep < 3; wrep++) {
        const int w = tow + wrep * TOW;
        const __half* qg = g_qkv + (((size_t)w * 3 + 0) * NHEAD + h) * (LTOK * HD);
        const __half* kg = g_qkv + (((size_t)w * 3 + 1) * NHEAD + h) * (LTOK * HD);
        const __half* vg = g_qkv + (((size_t)w * 3 + 2) * NHEAD + h) * (LTOK * HD);

        __syncthreads();
        for (int e = tid; e < LTOK * 4; e += 288) {
            int row = e >> 2, c4 = e & 3;
            uint32_t off = row * AROW + c4 * 16;
            *reinterpret_cast<uint4*>(sm + SQ_OFF + off) =
                *reinterpret_cast<const uint4*>(qg + row * HD + c4 * 8);
            *reinterpret_cast<uint4*>(sm + SK_OFF + off) =
                *reinterpret_cast<const uint4*>(kg + row * HD + c4 * 8);
            *reinterpret_cast<uint4*>(sm + SV_OFF + off) =
                *reinterpret_cast<const uint4*>(vg + row * HD + c4 * 8);
        }
        __syncthreads();

        uint32_t aq[2][4];
#pragma unroll
        for (int ks = 0; ks < 2; ks++)
            ldsm4(aq[ks], smb + SQ_OFF + (r0 + r8 + (g & 1) * 8) * AROW
                              + (ks * 16 + (g >> 1) * 8) * 2);

        float oacc[4][4];
#pragma unroll
        for (int i = 0; i < 4; i++)
#pragma unroll
            for (int c = 0; c < 4; c++) oacc[i][c] = 0.0f;
        float ls0 = 0.0f, ls1 = 0.0f;

        const float* mrow0 = mask + ((size_t)w * LTOK + r0 + gid) * LTOK;
        const float* mrow1 = mrow0 + 8 * LTOK;

#pragma unroll 3
        for (int nc = 0; nc < 9; nc++) {
            float sacc[2][4] = {{0.f, 0.f, 0.f, 0.f}, {0.f, 0.f, 0.f, 0.f}};
#pragma unroll
            for (int ks = 0; ks < 2; ks++) {
                uint32_t kb[4];
                ldsm4(kb, smb + SK_OFF + (nc * 16 + r8 + (g >> 1) * 8) * AROW
                              + (ks * 16 + (g & 1) * 8) * 2);
                mma16816h(sacc[0], aq[ks], kb + 0);
                mma16816h(sacc[1], aq[ks], kb + 2);
            }
            uint32_t pa[4];
#pragma unroll
            for (int t2 = 0; t2 < 2; t2++) {
                int col = nc * 16 + t2 * 8 + qid * 2;
                float2 b0 = __half22float2(*reinterpret_cast<const __half2*>(sb0 + col));
                float2 b1 = __half22float2(*reinterpret_cast<const __half2*>(sb1 + col));
                float2 m0 = *reinterpret_cast<const float2*>(mrow0 + col);
                float2 m1 = *reinterpret_cast<const float2*>(mrow1 + col);
                float p0 = exp_fma(sacc[t2][0] + b0.x + m0.x);
                float p1 = exp_fma(sacc[t2][1] + b0.y + m0.y);
                float p2 = exp_fma(sacc[t2][2] + b1.x + m1.x);
                float p3 = exp_fma(sacc[t2][3] + b1.y + m1.y);
                ls0 += p0 + p1;
                ls1 += p2 + p3;
                pa[2 * t2 + 0] = packh2(p0, p1);
                pa[2 * t2 + 1] = packh2(p2, p3);
            }
#pragma unroll
            for (int dh = 0; dh < 2; dh++) {
                uint32_t vb[4];
                ldsm4t(vb, smb + SV_OFF + (nc * 16 + (g & 1) * 8 + r8) * AROW
                               + (dh * 16 + (g >> 1) * 8) * 2);
                mma16816h(oacc[dh * 2 + 0], pa, vb + 0);
                mma16816h(oacc[dh * 2 + 1], pa, vb + 2);
            }
        }

        ls0 += __shfl_xor_sync(0xFFFFFFFFu, ls0, 1);
        ls0 += __shfl_xor_sync(0xFFFFFFFFu, ls0, 2);
        ls1 += __shfl_xor_sync(0xFFFFFFFFu, ls1, 1);
        ls1 += __shfl_xor_sync(0xFFFFFFFFu, ls1, 2);
        const float ri0 = 1.0f / ls0;
        const float ri1 = 1.0f / ls1;

        __half* ob0 = g_att + ((size_t)w * LTOK + r0 + gid) * DIM + h * HD;
        __half* ob1 = ob0 + 8 * DIM;
#pragma unroll
        for (int dt = 0; dt < 4; dt++) {
            *reinterpret_cast<uint32_t*>(ob0 + dt * 8 + qid * 2) =
                packh2(oacc[dt][0] * ri0, oacc[dt][1] * ri0);
            *reinterpret_cast<uint32_t*>(ob1 + dt * 8 + qid * 2) =
                packh2(oacc[dt][2] * ri1, oacc[dt][3] * ri1);
        }
    }
}

// ---------------------------------------------------------------------------
// Launch. Inputs: 0 x, 1 mask, 2 w1, 3 b1, 4 w2, 5 b2, 6 bias_table
// ---------------------------------------------------------------------------
extern "C" void kernel_launch(void* const* d_in, const int* in_sizes, int n_in,
                              void* d_out, int out_size) {
    const float* x     = (const float*)d_in[0];
    const float* mask  = (const float*)d_in[1];
    const float* w1    = (const float*)d_in[2];
    const float* b1    = (const float*)d_in[3];
    const float* w2    = (const float*)d_in[4];
    const float* b2    = (const float*)d_in[5];
    const float* table = (const float*)d_in[6];
    float* out = (float*)d_out;

    static bool attr_done = false;
    if (!attr_done) {
        cudaFuncSetAttribute(tc_gemm_qkv,
                             cudaFuncAttributeMaxDynamicSharedMemorySize, QKV_SMEM);
        cudaFuncSetAttribute(tc_gemm_out,
                             cudaFuncAttributeMaxDynamicSharedMemorySize, OUT_SMEM);
        cudaFuncSetAttribute(attn_mma_kernel,
                             cudaFuncAttributeMaxDynamicSharedMemorySize, ATTN_SMEM);
        attr_done = true;
    }

    wsplit_kernel<<<768, 192>>>(w1, w2);
    bias_gather_kernel<<<dim3(648, 6), 256>>>(table);
    tc_gemm_qkv<<<1620, 128, QKV_SMEM>>>(x, b1);
    attn_mma_kernel<<<TOW * NHEAD, 288, ATTN_SMEM>>>(mask);
    tc_gemm_out<<<1620, 128, OUT_SMEM>>>(b2, out);
}

// round 13
// speedup vs baseline: 2.0028x; 1.1211x over previous
#include <cuda_runtime.h>
#include <cuda_bf16.h>
#include <cuda_fp16.h>
#include <cstdint>
#include <cstddef>

// Problem constants
#define NW    720
#define LTOK  144
#define DIM   192
#define NHEAD 6
#define HD    32
#define TOW   240
#define SCALE 0.17677669529663687f   // 32^-0.5

// ---------------------------------------------------------------------------
// Scratch
// ---------------------------------------------------------------------------
__device__ __half g_qkv[(size_t)NW * 3 * NHEAD * LTOK * HD];  // fp16 [w][t][h][l][d]
__device__ float g_bias[(size_t)TOW * NHEAD * LTOK * LTOK];   // [tow*6+h][i*144+j]
__device__ __half g_att[(size_t)NW * LTOK * DIM];             // fp16 [w][l][h*32+d]
__device__ __half g_w1h[576 * 192], g_w1l[576 * 192];         // fp16 planes, Q pre-scaled
__device__ __half g_w2h[192 * 192], g_w2l[192 * 192];         // fp16 planes

__device__ __forceinline__ int posidx(int a, int b) {
    int za = a / 72, ha = (a % 72) / 12, wa = a % 12;
    int zb = b / 72, hb = (b % 72) / 12, wb = b % 12;
    return 828 * (za + 2 * zb) + 23 * (ha + 6 * hb) + (wa - wb + 11);
}

__device__ __forceinline__ uint32_t smem_u32(const void* p) {
    uint32_t a;
    asm("{ .reg .u64 t; cvta.to.shared.u64 t, %1; cvt.u32.u64 %0, t; }"
        : "=r"(a) : "l"(p));
    return a;
}
__device__ __forceinline__ uint32_t packh2(float a, float b) {
    __half2 t = __floats2half2_rn(a, b);
    return *reinterpret_cast<uint32_t*>(&t);
}
__device__ __forceinline__ void ldsm4(uint32_t* r, uint32_t addr) {
    asm volatile("ldmatrix.sync.aligned.m8n8.x4.shared.b16 {%0,%1,%2,%3}, [%4];"
                 : "=r"(r[0]), "=r"(r[1]), "=r"(r[2]), "=r"(r[3]) : "r"(addr));
}
__device__ __forceinline__ void ldsm4t(uint32_t* r, uint32_t addr) {
    asm volatile("ldmatrix.sync.aligned.m8n8.x4.trans.shared.b16 {%0,%1,%2,%3}, [%4];"
                 : "=r"(r[0]), "=r"(r[1]), "=r"(r[2]), "=r"(r[3]) : "r"(addr));
}
__device__ __forceinline__ void mma16816h(float* d, const uint32_t* a, const uint32_t* b) {
    asm volatile(
        "mma.sync.aligned.m16n8k16.row.col.f32.f16.f16.f32 "
        "{%0,%1,%2,%3}, {%4,%5,%6,%7}, {%8,%9}, {%0,%1,%2,%3};"
        : "+f"(d[0]), "+f"(d[1]), "+f"(d[2]), "+f"(d[3])
        : "r"(a[0]), "r"(a[1]), "r"(a[2]), "r"(a[3]), "r"(b[0]), "r"(b[1]));
}

// FFMA-pipe exponential. rel err ~3e-8 for moderate |x|.
__device__ __forceinline__ float exp_fma(float x) {
    float t = x * 1.4426950408889634f;
    float r = rintf(t);
    float f = t - r;
    float p = 1.5423875e-4f;
    p = p * f + 1.3333558e-3f;
    p = p * f + 9.6181291e-3f;
    p = p * f + 5.5504109e-2f;
    p = p * f + 2.4022651e-1f;
    p = p * f + 6.9314718e-1f;
    p = p * f + 1.0f;
    int e = (int)r;
    float s = __int_as_float((e + 127) << 23);
    return s * p;
}

// ---------------------------------------------------------------------------
// K-1: weight split prep -> fp16 hi/lo planes (w1 Q-rows pre-scaled).
// ---------------------------------------------------------------------------
__global__ void wsplit_kernel(const float* __restrict__ w1,
                              const float* __restrict__ w2) {
    const int row = blockIdx.x, col = threadIdx.x;
    if (row < 576) {
        float v = w1[row * 192 + col];
        if (row < 192) v *= SCALE;
        __half h = __float2half(v);
        g_w1h[row * 192 + col] = h;
        g_w1l[row * 192 + col] = __float2half(v - __half2float(h));
    } else {
        int r = row - 576;
        float v = w2[r * 192 + col];
        __half h = __float2half(v);
        g_w2h[r * 192 + col] = h;
        g_w2l[r * 192 + col] = __float2half(v - __half2float(h));
    }
}

// ---------------------------------------------------------------------------
// K0: bias gather/transpose
// ---------------------------------------------------------------------------
__global__ void bias_gather_kernel(const float* __restrict__ table) {
    __shared__ float tile[32][241];
    const int ij0 = blockIdx.x * 32;
    const int tt0 = blockIdx.y * 240;
    const int tid = threadIdx.x;

    for (int e = tid; e < 32 * 240; e += 256) {
        int ii = e / 240, tt = e % 240;
        int ij = ij0 + ii;
        int a = ij / LTOK, b = ij % LTOK;
        tile[ii][tt] = table[(size_t)posidx(a, b) * (TOW * NHEAD) + tt0 + tt];
    }
    __syncthreads();
    for (int e = tid; e < 32 * 240; e += 256) {
        int tt = e / 32, c = e % 32;
        g_bias[(size_t)(tt0 + tt) * (LTOK * LTOK) + ij0 + c] = tile[c][tt];
    }
}

// ---------------------------------------------------------------------------
// K1: qkv GEMM, 2-term fp16: A = x fp16 (single plane), B = w1 fp16 hi/lo.
// 128 thr, BM=64, grid 1620 (2 CTA/SM). C = A*Bh + A*Bl, fp32 acc,
// fp16 scatter-store to g_qkv with SCALE-folded bias on Q cols.
// ---------------------------------------------------------------------------
#define ROWB  400
#define QA_OFF 0
#define QBH_OFF (64 * ROWB)
#define QBL_OFF (2 * 64 * ROWB)
#define QKV_SMEM (3 * 64 * ROWB)        // 76800

__global__ __launch_bounds__(128)
void tc_gemm_qkv(const float* __restrict__ x, const float* __restrict__ bias) {
    extern __shared__ __align__(16) char sm[];
    const uint32_t smb = smem_u32(sm);
    const int tid = threadIdx.x;
    const int wid = tid >> 5, lane = tid & 31;
    const int m0 = blockIdx.x * 64;

    // A fill: 64 x 192 fp32 -> fp16 single plane
    for (int e = tid; e < 64 * 48; e += 128) {
        int m = e / 48, k4 = e % 48;
        float4 v = *reinterpret_cast<const float4*>(x + (size_t)(m0 + m) * 192 + k4 * 4);
        *reinterpret_cast<uint2*>(sm + QA_OFF + m * ROWB + k4 * 8) =
            make_uint2(packh2(v.x, v.y), packh2(v.z, v.w));
    }

    const int wm = wid & 1, wn = wid >> 1;
    const int gid = lane >> 2, qid = lane & 3;
    const int g = lane >> 3, r8 = lane & 7;

    for (int nt = 0; nt < 9; nt++) {
        if (nt) __syncthreads();
        for (int e = tid; e < 64 * 24; e += 128) {
            int n = e / 24, c = e % 24;
            uint32_t off = n * ROWB + c * 16;
            *reinterpret_cast<uint4*>(sm + QBH_OFF + off) =
                *reinterpret_cast<const uint4*>(g_w1h + (size_t)(nt * 64 + n) * 192 + c * 8);
            *reinterpret_cast<uint4*>(sm + QBL_OFF + off) =
                *reinterpret_cast<const uint4*>(g_w1l + (size_t)(nt * 64 + n) * 192 + c * 8);
        }
        __syncthreads();

        float acc[2][4][4];
#pragma unroll
        for (int i = 0; i < 2; i++)
#pragma unroll
            for (int j = 0; j < 4; j++)
#pragma unroll
                for (int c = 0; c < 4; c++) acc[i][j][c] = 0.0f;

#pragma unroll 3
        for (int ks = 0; ks < 12; ks++) {
            const int k0 = ks * 16;
            uint32_t aa[2][4];
#pragma unroll
            for (int mt = 0; mt < 2; mt++) {
                uint32_t row = wm * 32 + mt * 16 + r8 + (g & 1) * 8;
                uint32_t koff = (k0 + (g >> 1) * 8) * 2;
                ldsm4(aa[mt], smb + QA_OFF + row * ROWB + koff);
            }
            uint32_t bh[4][2], bl[4][2];
#pragma unroll
            for (int pr = 0; pr < 2; pr++) {
                uint32_t row = wn * 32 + pr * 16 + r8 + (g >> 1) * 8;
                uint32_t koff = (k0 + (g & 1) * 8) * 2;
                uint32_t th[4], tl[4];
                ldsm4(th, smb + QBH_OFF + row * ROWB + koff);
                ldsm4(tl, smb + QBL_OFF + row * ROWB + koff);
                bh[pr * 2 + 0][0] = th[0]; bh[pr * 2 + 0][1] = th[1];
                bh[pr * 2 + 1][0] = th[2]; bh[pr * 2 + 1][1] = th[3];
                bl[pr * 2 + 0][0] = tl[0]; bl[pr * 2 + 0][1] = tl[1];
                bl[pr * 2 + 1][0] = tl[2]; bl[pr * 2 + 1][1] = tl[3];
            }
#pragma unroll
            for (int mt = 0; mt < 2; mt++)
#pragma unroll
                for (int ntn = 0; ntn < 4; ntn++) {
                    mma16816h(acc[mt][ntn], aa[mt], bh[ntn]);
                    mma16816h(acc[mt][ntn], aa[mt], bl[ntn]);
                }
        }

        const int cbase = nt * 64 + wn * 32;
#pragma unroll
        for (int ntn = 0; ntn < 4; ntn++) {
            const int c = cbase + ntn * 8 + qid * 2;
            float2 bv = *reinterpret_cast<const float2*>(bias + c);
            if (c < 192) { bv.x *= SCALE; bv.y *= SCALE; }
            const int t = c / DIM, hh = (c % DIM) / HD, d = c % HD;
#pragma unroll
            for (int mt = 0; mt < 2; mt++) {
#pragma unroll
                for (int half = 0; half < 2; half++) {
                    const int m = m0 + wm * 32 + mt * 16 + gid + half * 8;
                    const int w = m / LTOK, l = m % LTOK;
                    *reinterpret_cast<uint32_t*>(
                        g_qkv + ((((size_t)w * 3 + t) * NHEAD + hh) * LTOK + l) * HD + d)
                        = packh2(acc[mt][ntn][half * 2 + 0] + bv.x,
                                 acc[mt][ntn][half * 2 + 1] + bv.y);
                }
            }
        }
    }
}

// ---------------------------------------------------------------------------
// K3: out-proj GEMM, fp16 2-term (R12 version).
// ---------------------------------------------------------------------------
#define OA_OFF 0
#define OBH_OFF (64 * ROWB)
#define OBL_OFF (2 * 64 * ROWB)
#define OUT_SMEM (3 * 64 * ROWB)        // 76800

__global__ __launch_bounds__(128)
void tc_gemm_out(const float* __restrict__ bias, float* __restrict__ C) {
    extern __shared__ __align__(16) char sm[];
    const uint32_t smb = smem_u32(sm);
    const int tid = threadIdx.x;
    const int wid = tid >> 5, lane = tid & 31;
    const int m0 = blockIdx.x * 64;

    for (int e = tid; e < 64 * 24; e += 128) {
        int m = e / 24, c4 = e % 24;
        *reinterpret_cast<uint4*>(sm + OA_OFF + m * ROWB + c4 * 16) =
            *reinterpret_cast<const uint4*>(g_att + (size_t)(m0 + m) * 192 + c4 * 8);
    }

    const int wm = wid & 1, wn = wid >> 1;
    const int gid = lane >> 2, qid = lane & 3;
    const int g = lane >> 3, r8 = lane & 7;

    for (int nt = 0; nt < 3; nt++) {
        if (nt) __syncthreads();
        for (int e = tid; e < 64 * 24; e += 128) {
            int n = e / 24, c = e % 24;
            uint32_t off = n * ROWB + c * 16;
            *reinterpret_cast<uint4*>(sm + OBH_OFF + off) =
                *reinterpret_cast<const uint4*>(g_w2h + (size_t)(nt * 64 + n) * 192 + c * 8);
            *reinterpret_cast<uint4*>(sm + OBL_OFF + off) =
                *reinterpret_cast<const uint4*>(g_w2l + (size_t)(nt * 64 + n) * 192 + c * 8);
        }
        __syncthreads();

        float acc[2][4][4];
#pragma unroll
        for (int i = 0; i < 2; i++)
#pragma unroll
            for (int j = 0; j < 4; j++)
#pragma unroll
                for (int c = 0; c < 4; c++) acc[i][j][c] = 0.0f;

#pragma unroll 3
        for (int ks = 0; ks < 12; ks++) {
            const int k0 = ks * 16;
            uint32_t aa[2][4];
#pragma unroll
            for (int mt = 0; mt < 2; mt++) {
                uint32_t row = wm * 32 + mt * 16 + r8 + (g & 1) * 8;
                uint32_t koff = (k0 + (g >> 1) * 8) * 2;
                ldsm4(aa[mt], smb + OA_OFF + row * ROWB + koff);
            }
            uint32_t bh[4][2], bl[4][2];
#pragma unroll
            for (int pr = 0; pr < 2; pr++) {
                uint32_t row = wn * 32 + pr * 16 + r8 + (g >> 1) * 8;
                uint32_t koff = (k0 + (g & 1) * 8) * 2;
                uint32_t th[4], tl[4];
                ldsm4(th, smb + OBH_OFF + row * ROWB + koff);
                ldsm4(tl, smb + OBL_OFF + row * ROWB + koff);
                bh[pr * 2 + 0][0] = th[0]; bh[pr * 2 + 0][1] = th[1];
                bh[pr * 2 + 1][0] = th[2]; bh[pr * 2 + 1][1] = th[3];
                bl[pr * 2 + 0][0] = tl[0]; bl[pr * 2 + 0][1] = tl[1];
                bl[pr * 2 + 1][0] = tl[2]; bl[pr * 2 + 1][1] = tl[3];
            }
#pragma unroll
            for (int mt = 0; mt < 2; mt++)
#pragma unroll
                for (int ntn = 0; ntn < 4; ntn++) {
                    mma16816h(acc[mt][ntn], aa[mt], bh[ntn]);
                    mma16816h(acc[mt][ntn], aa[mt], bl[ntn]);
                }
        }

        const int cbase = nt * 64 + wn * 32;
#pragma unroll
        for (int ntn = 0; ntn < 4; ntn++) {
            const int c = cbase + ntn * 8 + qid * 2;
            const float2 bv = *reinterpret_cast<const float2*>(bias + c);
#pragma unroll
            for (int mt = 0; mt < 2; mt++) {
#pragma unroll
                for (int half = 0; half < 2; half++) {
                    const int m = m0 + wm * 32 + mt * 16 + gid + half * 8;
                    *reinterpret_cast<float2*>(C + (size_t)m * DIM + c) =
                        make_float2(acc[mt][ntn][half * 2 + 0] + bv.x,
                                    acc[mt][ntn][half * 2 + 1] + bv.y);
                }
            }
        }
    }
}

// ---------------------------------------------------------------------------
// K2: HMMA fp16 attention (R12 winner, unchanged).
// ---------------------------------------------------------------------------
#define AROW 80
#define SQ_OFF 0
#define SK_OFF (LTOK * AROW)
#define SV_OFF (2 * LTOK * AROW)
#define SB_OFF (3 * LTOK * AROW)
#define SBSTRIDE 152
#define ATTN_SMEM (SB_OFF + LTOK * SBSTRIDE * 2)

__global__ __launch_bounds__(288)
void attn_mma_kernel(const float* __restrict__ mask) {
    extern __shared__ __align__(16) char sm[];
    const int bx = blockIdx.x;
    const int tow = bx / NHEAD;
    const int h = bx % NHEAD;
    const int tid = threadIdx.x;
    const int warp = tid >> 5, lane = tid & 31;
    const int gid = lane >> 2, qid = lane & 3;
    const int g = lane >> 3, r8 = lane & 7;
    const uint32_t smb = smem_u32(sm);
    const int r0 = warp * 16;

    const float* bias_base = g_bias + ((size_t)tow * NHEAD + h) * (LTOK * LTOK);
    for (int e = tid; e < LTOK * 72; e += 288) {
        int row = e / 72, c2 = e % 72;
        float2 v = *reinterpret_cast<const float2*>(bias_base + row * LTOK + c2 * 2);
        *reinterpret_cast<uint32_t*>(sm + SB_OFF + (row * SBSTRIDE + c2 * 2) * 2) =
            packh2(v.x, v.y);
    }

    const __half* sb0 = reinterpret_cast<const __half*>(sm + SB_OFF) + (r0 + gid) * SBSTRIDE;
    const __half* sb1 = sb0 + 8 * SBSTRIDE;

    for (int wrep = 0; wrep < 3; wrep++) {
        const int w = tow + wrep * TOW;
        const __half* qg = g_qkv + (((size_t)w * 3 + 0) * NHEAD + h) * (LTOK * HD);
        const __half* kg = g_qkv + (((size_t)w * 3 + 1) * NHEAD + h) * (LTOK * HD);
        const __half* vg = g_qkv + (((size_t)w * 3 + 2) * NHEAD + h) * (LTOK * HD);

        __syncthreads();
        for (int e = tid; e < LTOK * 4; e += 288) {
            int row = e >> 2, c4 = e & 3;
            uint32_t off = row * AROW + c4 * 16;
            *reinterpret_cast<uint4*>(sm + SQ_OFF + off) =
                *reinterpret_cast<const uint4*>(qg + row * HD + c4 * 8);
            *reinterpret_cast<uint4*>(sm + SK_OFF + off) =
                *reinterpret_cast<const uint4*>(kg + row * HD + c4 * 8);
            *reinterpret_cast<uint4*>(sm + SV_OFF + off) =
                *reinterpret_cast<const uint4*>(vg + row * HD + c4 * 8);
        }
        __syncthreads();

        uint32_t aq[2][4];
#pragma unroll
        for (int ks = 0; ks < 2; ks++)
            ldsm4(aq[ks], smb + SQ_OFF + (r0 + r8 + (g & 1) * 8) * AROW
                              + (ks * 16 + (g >> 1) * 8) * 2);

        float oacc[4][4];
#pragma unroll
        for (int i = 0; i < 4; i++)
#pragma unroll
            for (int c = 0; c < 4; c++) oacc[i][c] = 0.0f;
        float ls0 = 0.0f, ls1 = 0.0f;

        const float* mrow0 = mask + ((size_t)w * LTOK + r0 + gid) * LTOK;
        const float* mrow1 = mrow0 + 8 * LTOK;

#pragma unroll 3
        for (int nc = 0; nc < 9; nc++) {
            float sacc[2][4] = {{0.f, 0.f, 0.f, 0.f}, {0.f, 0.f, 0.f, 0.f}};
#pragma unroll
            for (int ks = 0; ks < 2; ks++) {
                uint32_t kb[4];
                ldsm4(kb, smb + SK_OFF + (nc * 16 + r8 + (g >> 1) * 8) * AROW
                              + (ks * 16 + (g & 1) * 8) * 2);
                mma16816h(sacc[0], aq[ks], kb + 0);
                mma16816h(sacc[1], aq[ks], kb + 2);
            }
            uint32_t pa[4];
#pragma unroll
            for (int t2 = 0; t2 < 2; t2++) {
                int col = nc * 16 + t2 * 8 + qid * 2;
                float2 b0 = __half22float2(*reinterpret_cast<const __half2*>(sb0 + col));
                float2 b1 = __half22float2(*reinterpret_cast<const __half2*>(sb1 + col));
                float2 m0 = *reinterpret_cast<const float2*>(mrow0 + col);
                float2 m1 = *reinterpret_cast<const float2*>(mrow1 + col);
                float p0 = exp_fma(sacc[t2][0] + b0.x + m0.x);
                float p1 = exp_fma(sacc[t2][1] + b0.y + m0.y);
                float p2 = exp_fma(sacc[t2][2] + b1.x + m1.x);
                float p3 = exp_fma(sacc[t2][3] + b1.y + m1.y);
                ls0 += p0 + p1;
                ls1 += p2 + p3;
                pa[2 * t2 + 0] = packh2(p0, p1);
                pa[2 * t2 + 1] = packh2(p2, p3);
            }
#pragma unroll
            for (int dh = 0; dh < 2; dh++) {
                uint32_t vb[4];
                ldsm4t(vb, smb + SV_OFF + (nc * 16 + (g & 1) * 8 + r8) * AROW
                               + (dh * 16 + (g >> 1) * 8) * 2);
                mma16816h(oacc[dh * 2 + 0], pa, vb + 0);
                mma16816h(oacc[dh * 2 + 1], pa, vb + 2);
            }
        }

        ls0 += __shfl_xor_sync(0xFFFFFFFFu, ls0, 1);
        ls0 += __shfl_xor_sync(0xFFFFFFFFu, ls0, 2);
        ls1 += __shfl_xor_sync(0xFFFFFFFFu, ls1, 1);
        ls1 += __shfl_xor_sync(0xFFFFFFFFu, ls1, 2);
        const float ri0 = 1.0f / ls0;
        const float ri1 = 1.0f / ls1;

        __half* ob0 = g_att + ((size_t)w * LTOK + r0 + gid) * DIM + h * HD;
        __half* ob1 = ob0 + 8 * DIM;
#pragma unroll
        for (int dt = 0; dt < 4; dt++) {
            *reinterpret_cast<uint32_t*>(ob0 + dt * 8 + qid * 2) =
                packh2(oacc[dt][0] * ri0, oacc[dt][1] * ri0);
            *reinterpret_cast<uint32_t*>(ob1 + dt * 8 + qid * 2) =
                packh2(oacc[dt][2] * ri1, oacc[dt][3] * ri1);
        }
    }
}

// ---------------------------------------------------------------------------
// Launch. Inputs: 0 x, 1 mask, 2 w1, 3 b1, 4 w2, 5 b2, 6 bias_table
// ---------------------------------------------------------------------------
extern "C" void kernel_launch(void* const* d_in, const int* in_sizes, int n_in,
                              void* d_out, int out_size) {
    const float* x     = (const float*)d_in[0];
    const float* mask  = (const float*)d_in[1];
    const float* w1    = (const float*)d_in[2];
    const float* b1    = (const float*)d_in[3];
    const float* w2    = (const float*)d_in[4];
    const float* b2    = (const float*)d_in[5];
    const float* table = (const float*)d_in[6];
    float* out = (float*)d_out;

    static bool attr_done = false;
    if (!attr_done) {
        cudaFuncSetAttribute(tc_gemm_qkv,
                             cudaFuncAttributeMaxDynamicSharedMemorySize, QKV_SMEM);
        cudaFuncSetAttribute(tc_gemm_out,
                             cudaFuncAttributeMaxDynamicSharedMemorySize, OUT_SMEM);
        cudaFuncSetAttribute(attn_mma_kernel,
                             cudaFuncAttributeMaxDynamicSharedMemorySize, ATTN_SMEM);
        attr_done = true;
    }

    wsplit_kernel<<<768, 192>>>(w1, w2);
    bias_gather_kernel<<<dim3(648, 6), 256>>>(table);
    tc_gemm_qkv<<<1620, 128, QKV_SMEM>>>(x, b1);
    attn_mma_kernel<<<TOW * NHEAD, 288, ATTN_SMEM>>>(mask);
    tc_gemm_out<<<1620, 128, OUT_SMEM>>>(b2, out);
}

// round 14
// speedup vs baseline: 2.0560x; 1.0265x over previous
#include <cuda_runtime.h>
#include <cuda_bf16.h>
#include <cuda_fp16.h>
#include <cstdint>
#include <cstddef>

// Problem constants
#define NW    720
#define LTOK  144
#define DIM   192
#define NHEAD 6
#define HD    32
#define TOW   240
#define SCALE 0.17677669529663687f   // 32^-0.5

// ---------------------------------------------------------------------------
// Scratch
// ---------------------------------------------------------------------------
__device__ __half g_qkv[(size_t)NW * 3 * NHEAD * LTOK * HD];  // fp16 [w][t][h][l][d]
__device__ float g_bias[(size_t)TOW * NHEAD * LTOK * LTOK];   // [tow*6+h][i*144+j]
__device__ __half g_att[(size_t)NW * LTOK * DIM];             // fp16 [w][l][h*32+d]
__device__ __half g_w1h[576 * 192], g_w1l[576 * 192];         // fp16 planes, Q pre-scaled
__device__ __half g_w2h[192 * 192], g_w2l[192 * 192];         // fp16 planes

__device__ __forceinline__ int posidx(int a, int b) {
    int za = a / 72, ha = (a % 72) / 12, wa = a % 12;
    int zb = b / 72, hb = (b % 72) / 12, wb = b % 12;
    return 828 * (za + 2 * zb) + 23 * (ha + 6 * hb) + (wa - wb + 11);
}

__device__ __forceinline__ uint32_t smem_u32(const void* p) {
    uint32_t a;
    asm("{ .reg .u64 t; cvta.to.shared.u64 t, %1; cvt.u32.u64 %0, t; }"
        : "=r"(a) : "l"(p));
    return a;
}
__device__ __forceinline__ uint32_t packh2(float a, float b) {
    __half2 t = __floats2half2_rn(a, b);
    return *reinterpret_cast<uint32_t*>(&t);
}
__device__ __forceinline__ void ldsm4(uint32_t* r, uint32_t addr) {
    asm volatile("ldmatrix.sync.aligned.m8n8.x4.shared.b16 {%0,%1,%2,%3}, [%4];"
                 : "=r"(r[0]), "=r"(r[1]), "=r"(r[2]), "=r"(r[3]) : "r"(addr));
}
__device__ __forceinline__ void ldsm4t(uint32_t* r, uint32_t addr) {
    asm volatile("ldmatrix.sync.aligned.m8n8.x4.trans.shared.b16 {%0,%1,%2,%3}, [%4];"
                 : "=r"(r[0]), "=r"(r[1]), "=r"(r[2]), "=r"(r[3]) : "r"(addr));
}
__device__ __forceinline__ void mma16816h(float* d, const uint32_t* a, const uint32_t* b) {
    asm volatile(
        "mma.sync.aligned.m16n8k16.row.col.f32.f16.f16.f32 "
        "{%0,%1,%2,%3}, {%4,%5,%6,%7}, {%8,%9}, {%0,%1,%2,%3};"
        : "+f"(d[0]), "+f"(d[1]), "+f"(d[2]), "+f"(d[3])
        : "r"(a[0]), "r"(a[1]), "r"(a[2]), "r"(a[3]), "r"(b[0]), "r"(b[1]));
}

// FFMA-pipe exponential. rel err ~3e-8 for moderate |x|.
__device__ __forceinline__ float exp_fma(float x) {
    float t = x * 1.4426950408889634f;
    float r = rintf(t);
    float f = t - r;
    float p = 1.5423875e-4f;
    p = p * f + 1.3333558e-3f;
    p = p * f + 9.6181291e-3f;
    p = p * f + 5.5504109e-2f;
    p = p * f + 2.4022651e-1f;
    p = p * f + 6.9314718e-1f;
    p = p * f + 1.0f;
    int e = (int)r;
    float s = __int_as_float((e + 127) << 23);
    return s * p;
}

// ---------------------------------------------------------------------------
// K-1: weight split prep -> fp16 hi/lo planes (w1 Q-rows pre-scaled).
// ---------------------------------------------------------------------------
__global__ void wsplit_kernel(const float* __restrict__ w1,
                              const float* __restrict__ w2) {
    const int row = blockIdx.x, col = threadIdx.x;
    if (row < 576) {
        float v = w1[row * 192 + col];
        if (row < 192) v *= SCALE;
        __half h = __float2half(v);
        g_w1h[row * 192 + col] = h;
        g_w1l[row * 192 + col] = __float2half(v - __half2float(h));
    } else {
        int r = row - 576;
        float v = w2[r * 192 + col];
        __half h = __float2half(v);
        g_w2h[r * 192 + col] = h;
        g_w2l[r * 192 + col] = __float2half(v - __half2float(h));
    }
}

// ---------------------------------------------------------------------------
// K0: bias gather/transpose
// ---------------------------------------------------------------------------
__global__ void bias_gather_kernel(const float* __restrict__ table) {
    __shared__ float tile[32][241];
    const int ij0 = blockIdx.x * 32;
    const int tt0 = blockIdx.y * 240;
    const int tid = threadIdx.x;

    for (int e = tid; e < 32 * 240; e += 256) {
        int ii = e / 240, tt = e % 240;
        int ij = ij0 + ii;
        int a = ij / LTOK, b = ij % LTOK;
        tile[ii][tt] = table[(size_t)posidx(a, b) * (TOW * NHEAD) + tt0 + tt];
    }
    __syncthreads();
    for (int e = tid; e < 32 * 240; e += 256) {
        int tt = e / 32, c = e % 32;
        g_bias[(size_t)(tt0 + tt) * (LTOK * LTOK) + ij0 + c] = tile[c][tt];
    }
}

// ---------------------------------------------------------------------------
// K1: qkv GEMM, 2-term fp16. BM=128, 256 thr (8 warps: 4m x 2n of 32x32),
// grid 810, smem 102.4KB -> 2 CTA/SM (16 warps/SM, 4/SMSP).
// A = x fp16 single plane; B = w1 fp16 hi/lo. fp16 scatter-store to g_qkv.
// ---------------------------------------------------------------------------
#define ROWB  400
#define QA_OFF 0
#define QBH_OFF (128 * ROWB)                 // 51200
#define QBL_OFF (QBH_OFF + 64 * ROWB)        // 76800
#define QKV_SMEM (QBL_OFF + 64 * ROWB)       // 102400

__global__ __launch_bounds__(256)
void tc_gemm_qkv(const float* __restrict__ x, const float* __restrict__ bias) {
    extern __shared__ __align__(16) char sm[];
    const uint32_t smb = smem_u32(sm);
    const int tid = threadIdx.x;
    const int wid = tid >> 5, lane = tid & 31;
    const int m0 = blockIdx.x * 128;

    // A fill: 128 x 192 fp32 -> fp16 single plane
    for (int e = tid; e < 128 * 48; e += 256) {
        int m = e / 48, k4 = e % 48;
        float4 v = *reinterpret_cast<const float4*>(x + (size_t)(m0 + m) * 192 + k4 * 4);
        *reinterpret_cast<uint2*>(sm + QA_OFF + m * ROWB + k4 * 8) =
            make_uint2(packh2(v.x, v.y), packh2(v.z, v.w));
    }

    const int wm = wid & 3, wn = wid >> 2;       // 4x2 warp grid
    const int gid = lane >> 2, qid = lane & 3;
    const int g = lane >> 3, r8 = lane & 7;

    for (int nt = 0; nt < 9; nt++) {
        if (nt) __syncthreads();
        for (int e = tid; e < 64 * 24; e += 256) {
            int n = e / 24, c = e % 24;
            uint32_t off = n * ROWB + c * 16;
            *reinterpret_cast<uint4*>(sm + QBH_OFF + off) =
                *reinterpret_cast<const uint4*>(g_w1h + (size_t)(nt * 64 + n) * 192 + c * 8);
            *reinterpret_cast<uint4*>(sm + QBL_OFF + off) =
                *reinterpret_cast<const uint4*>(g_w1l + (size_t)(nt * 64 + n) * 192 + c * 8);
        }
        __syncthreads();

        float acc[2][4][4];
#pragma unroll
        for (int i = 0; i < 2; i++)
#pragma unroll
            for (int j = 0; j < 4; j++)
#pragma unroll
                for (int c = 0; c < 4; c++) acc[i][j][c] = 0.0f;

#pragma unroll 3
        for (int ks = 0; ks < 12; ks++) {
            const int k0 = ks * 16;
            uint32_t aa[2][4];
#pragma unroll
            for (int mt = 0; mt < 2; mt++) {
                uint32_t row = wm * 32 + mt * 16 + r8 + (g & 1) * 8;
                uint32_t koff = (k0 + (g >> 1) * 8) * 2;
                ldsm4(aa[mt], smb + QA_OFF + row * ROWB + koff);
            }
            uint32_t bh[4][2], bl[4][2];
#pragma unroll
            for (int pr = 0; pr < 2; pr++) {
                uint32_t row = wn * 32 + pr * 16 + r8 + (g >> 1) * 8;
                uint32_t koff = (k0 + (g & 1) * 8) * 2;
                uint32_t th[4], tl[4];
                ldsm4(th, smb + QBH_OFF + row * ROWB + koff);
                ldsm4(tl, smb + QBL_OFF + row * ROWB + koff);
                bh[pr * 2 + 0][0] = th[0]; bh[pr * 2 + 0][1] = th[1];
                bh[pr * 2 + 1][0] = th[2]; bh[pr * 2 + 1][1] = th[3];
                bl[pr * 2 + 0][0] = tl[0]; bl[pr * 2 + 0][1] = tl[1];
                bl[pr * 2 + 1][0] = tl[2]; bl[pr * 2 + 1][1] = tl[3];
            }
#pragma unroll
            for (int mt = 0; mt < 2; mt++)
#pragma unroll
                for (int ntn = 0; ntn < 4; ntn++) {
                    mma16816h(acc[mt][ntn], aa[mt], bh[ntn]);
                    mma16816h(acc[mt][ntn], aa[mt], bl[ntn]);
                }
        }

        const int cbase = nt * 64 + wn * 32;
#pragma unroll
        for (int ntn = 0; ntn < 4; ntn++) {
            const int c = cbase + ntn * 8 + qid * 2;
            float2 bv = *reinterpret_cast<const float2*>(bias + c);
            if (c < 192) { bv.x *= SCALE; bv.y *= SCALE; }
            const int t = c / DIM, hh = (c % DIM) / HD, d = c % HD;
#pragma unroll
            for (int mt = 0; mt < 2; mt++) {
#pragma unroll
                for (int half = 0; half < 2; half++) {
                    const int m = m0 + wm * 32 + mt * 16 + gid + half * 8;
                    const int w = m / LTOK, l = m % LTOK;
                    *reinterpret_cast<uint32_t*>(
                        g_qkv + ((((size_t)w * 3 + t) * NHEAD + hh) * LTOK + l) * HD + d)
                        = packh2(acc[mt][ntn][half * 2 + 0] + bv.x,
                                 acc[mt][ntn][half * 2 + 1] + bv.y);
                }
            }
        }
    }
}

// ---------------------------------------------------------------------------
// K3: out-proj GEMM, fp16 2-term. BM=128, 256 thr, grid 810, 2 CTA/SM.
// ---------------------------------------------------------------------------
#define OA_OFF 0
#define OBH_OFF (128 * ROWB)
#define OBL_OFF (OBH_OFF + 64 * ROWB)
#define OUT_SMEM (OBL_OFF + 64 * ROWB)       // 102400

__global__ __launch_bounds__(256)
void tc_gemm_out(const float* __restrict__ bias, float* __restrict__ C) {
    extern __shared__ __align__(16) char sm[];
    const uint32_t smb = smem_u32(sm);
    const int tid = threadIdx.x;
    const int wid = tid >> 5, lane = tid & 31;
    const int m0 = blockIdx.x * 128;

    // A fill: pure fp16 copies (128 rows x 24 uint4)
    for (int e = tid; e < 128 * 24; e += 256) {
        int m = e / 24, c4 = e % 24;
        *reinterpret_cast<uint4*>(sm + OA_OFF + m * ROWB + c4 * 16) =
            *reinterpret_cast<const uint4*>(g_att + (size_t)(m0 + m) * 192 + c4 * 8);
    }

    const int wm = wid & 3, wn = wid >> 2;
    const int gid = lane >> 2, qid = lane & 3;
    const int g = lane >> 3, r8 = lane & 7;

    for (int nt = 0; nt < 3; nt++) {
        if (nt) __syncthreads();
        for (int e = tid; e < 64 * 24; e += 256) {
            int n = e / 24, c = e % 24;
            uint32_t off = n * ROWB + c * 16;
            *reinterpret_cast<uint4*>(sm + OBH_OFF + off) =
                *reinterpret_cast<const uint4*>(g_w2h + (size_t)(nt * 64 + n) * 192 + c * 8);
            *reinterpret_cast<uint4*>(sm + OBL_OFF + off) =
                *reinterpret_cast<const uint4*>(g_w2l + (size_t)(nt * 64 + n) * 192 + c * 8);
        }
        __syncthreads();

        float acc[2][4][4];
#pragma unroll
        for (int i = 0; i < 2; i++)
#pragma unroll
            for (int j = 0; j < 4; j++)
#pragma unroll
                for (int c = 0; c < 4; c++) acc[i][j][c] = 0.0f;

#pragma unroll 3
        for (int ks = 0; ks < 12; ks++) {
            const int k0 = ks * 16;
            uint32_t aa[2][4];
#pragma unroll
            for (int mt = 0; mt < 2; mt++) {
                uint32_t row = wm * 32 + mt * 16 + r8 + (g & 1) * 8;
                uint32_t koff = (k0 + (g >> 1) * 8) * 2;
                ldsm4(aa[mt], smb + OA_OFF + row * ROWB + koff);
            }
            uint32_t bh[4][2], bl[4][2];
#pragma unroll
            for (int pr = 0; pr < 2; pr++) {
                uint32_t row = wn * 32 + pr * 16 + r8 + (g >> 1) * 8;
                uint32_t koff = (k0 + (g & 1) * 8) * 2;
                uint32_t th[4], tl[4];
                ldsm4(th, smb + OBH_OFF + row * ROWB + koff);
                ldsm4(tl, smb + OBL_OFF + row * ROWB + koff);
                bh[pr * 2 + 0][0] = th[0]; bh[pr * 2 + 0][1] = th[1];
                bh[pr * 2 + 1][0] = th[2]; bh[pr * 2 + 1][1] = th[3];
                bl[pr * 2 + 0][0] = tl[0]; bl[pr * 2 + 0][1] = tl[1];
                bl[pr * 2 + 1][0] = tl[2]; bl[pr * 2 + 1][1] = tl[3];
            }
#pragma unroll
            for (int mt = 0; mt < 2; mt++)
#pragma unroll
                for (int ntn = 0; ntn < 4; ntn++) {
                    mma16816h(acc[mt][ntn], aa[mt], bh[ntn]);
                    mma16816h(acc[mt][ntn], aa[mt], bl[ntn]);
                }
        }

        const int cbase = nt * 64 + wn * 32;
#pragma unroll
        for (int ntn = 0; ntn < 4; ntn++) {
            const int c = cbase + ntn * 8 + qid * 2;
            const float2 bv = *reinterpret_cast<const float2*>(bias + c);
#pragma unroll
            for (int mt = 0; mt < 2; mt++) {
#pragma unroll
                for (int half = 0; half < 2; half++) {
                    const int m = m0 + wm * 32 + mt * 16 + gid + half * 8;
                    *reinterpret_cast<float2*>(C + (size_t)m * DIM + c) =
                        make_float2(acc[mt][ntn][half * 2 + 0] + bv.x,
                                    acc[mt][ntn][half * 2 + 1] + bv.y);
                }
            }
        }
    }
}

// ---------------------------------------------------------------------------
// K2: HMMA fp16 attention. SBSTRIDE 146 -> smem 76608 B -> 3 CTA/SM.
// (146 words*2 = 292B row stride; 73 words mod 32 = 9 -> quad rows hit
//  8 distinct banks; half2-aligned since 292 % 4 == 0.)
// ---------------------------------------------------------------------------
#define AROW 80
#define SQ_OFF 0
#define SK_OFF (LTOK * AROW)
#define SV_OFF (2 * LTOK * AROW)
#define SB_OFF (3 * LTOK * AROW)
#define SBSTRIDE 146
#define ATTN_SMEM (SB_OFF + LTOK * SBSTRIDE * 2)   // 76608

__global__ __launch_bounds__(288)
void attn_mma_kernel(const float* __restrict__ mask) {
    extern __shared__ __align__(16) char sm[];
    const int bx = blockIdx.x;
    const int tow = bx / NHEAD;
    const int h = bx % NHEAD;
    const int tid = threadIdx.x;
    const int warp = tid >> 5, lane = tid & 31;
    const int gid = lane >> 2, qid = lane & 3;
    const int g = lane >> 3, r8 = lane & 7;
    const uint32_t smb = smem_u32(sm);
    const int r0 = warp * 16;

    const float* bias_base = g_bias + ((size_t)tow * NHEAD + h) * (LTOK * LTOK);
    for (int e = tid; e < LTOK * 72; e += 288) {
        int row = e / 72, c2 = e % 72;
        float2 v = *reinterpret_cast<const float2*>(bias_base + row * LTOK + c2 * 2);
        *reinterpret_cast<uint32_t*>(sm + SB_OFF + (row * SBSTRIDE + c2 * 2) * 2) =
            packh2(v.x, v.y);
    }

    const __half* sb0 = reinterpret_cast<const __half*>(sm + SB_OFF) + (r0 + gid) * SBSTRIDE;
    const __half* sb1 = sb0 + 8 * SBSTRIDE;

    for (int wrep = 0; wrep < 3; wrep++) {
        const int w = tow + wrep * TOW;
        const __half* qg = g_qkv + (((size_t)w * 3 + 0) * NHEAD + h) * (LTOK * HD);
        const __half* kg = g_qkv + (((size_t)w * 3 + 1) * NHEAD + h) * (LTOK * HD);
        const __half* vg = g_qkv + (((size_t)w * 3 + 2) * NHEAD + h) * (LTOK * HD);

        __syncthreads();
        for (int e = tid; e < LTOK * 4; e += 288) {
            int row = e >> 2, c4 = e & 3;
            uint32_t off = row * AROW + c4 * 16;
            *reinterpret_cast<uint4*>(sm + SQ_OFF + off) =
                *reinterpret_cast<const uint4*>(qg + row * HD + c4 * 8);
            *reinterpret_cast<uint4*>(sm + SK_OFF + off) =
                *reinterpret_cast<const uint4*>(kg + row * HD + c4 * 8);
            *reinterpret_cast<uint4*>(sm + SV_OFF + off) =
                *reinterpret_cast<const uint4*>(vg + row * HD + c4 * 8);
        }
        __syncthreads();

        uint32_t aq[2][4];
#pragma unroll
        for (int ks = 0; ks < 2; ks++)
            ldsm4(aq[ks], smb + SQ_OFF + (r0 + r8 + (g & 1) * 8) * AROW
                              + (ks * 16 + (g >> 1) * 8) * 2);

        float oacc[4][4];
#pragma unroll
        for (int i = 0; i < 4; i++)
#pragma unroll
            for (int c = 0; c < 4; c++) oacc[i][c] = 0.0f;
        float ls0 = 0.0f, ls1 = 0.0f;

        const float* mrow0 = mask + ((size_t)w * LTOK + r0 + gid) * LTOK;
        const float* mrow1 = mrow0 + 8 * LTOK;

#pragma unroll 3
        for (int nc = 0; nc < 9; nc++) {
            float sacc[2][4] = {{0.f, 0.f, 0.f, 0.f}, {0.f, 0.f, 0.f, 0.f}};
#pragma unroll
            for (int ks = 0; ks < 2; ks++) {
                uint32_t kb[4];
                ldsm4(kb, smb + SK_OFF + (nc * 16 + r8 + (g >> 1) * 8) * AROW
                              + (ks * 16 + (g & 1) * 8) * 2);
                mma16816h(sacc[0], aq[ks], kb + 0);
                mma16816h(sacc[1], aq[ks], kb + 2);
            }
            uint32_t pa[4];
#pragma unroll
            for (int t2 = 0; t2 < 2; t2++) {
                int col = nc * 16 + t2 * 8 + qid * 2;
                float2 b0 = __half22float2(*reinterpret_cast<const __half2*>(sb0 + col));
                float2 b1 = __half22float2(*reinterpret_cast<const __half2*>(sb1 + col));
                float2 m0 = *reinterpret_cast<const float2*>(mrow0 + col);
                float2 m1 = *reinterpret_cast<const float2*>(mrow1 + col);
                float p0 = exp_fma(sacc[t2][0] + b0.x + m0.x);
                float p1 = exp_fma(sacc[t2][1] + b0.y + m0.y);
                float p2 = exp_fma(sacc[t2][2] + b1.x + m1.x);
                float p3 = exp_fma(sacc[t2][3] + b1.y + m1.y);
                ls0 += p0 + p1;
                ls1 += p2 + p3;
                pa[2 * t2 + 0] = packh2(p0, p1);
                pa[2 * t2 + 1] = packh2(p2, p3);
            }
#pragma unroll
            for (int dh = 0; dh < 2; dh++) {
                uint32_t vb[4];
                ldsm4t(vb, smb + SV_OFF + (nc * 16 + (g & 1) * 8 + r8) * AROW
                               + (dh * 16 + (g >> 1) * 8) * 2);
                mma16816h(oacc[dh * 2 + 0], pa, vb + 0);
                mma16816h(oacc[dh * 2 + 1], pa, vb + 2);
            }
        }

        ls0 += __shfl_xor_sync(0xFFFFFFFFu, ls0, 1);
        ls0 += __shfl_xor_sync(0xFFFFFFFFu, ls0, 2);
        ls1 += __shfl_xor_sync(0xFFFFFFFFu, ls1, 1);
        ls1 += __shfl_xor_sync(0xFFFFFFFFu, ls1, 2);
        const float ri0 = 1.0f / ls0;
        const float ri1 = 1.0f / ls1;

        __half* ob0 = g_att + ((size_t)w * LTOK + r0 + gid) * DIM + h * HD;
        __half* ob1 = ob0 + 8 * DIM;
#pragma unroll
        for (int dt = 0; dt < 4; dt++) {
            *reinterpret_cast<uint32_t*>(ob0 + dt * 8 + qid * 2) =
                packh2(oacc[dt][0] * ri0, oacc[dt][1] * ri0);
            *reinterpret_cast<uint32_t*>(ob1 + dt * 8 + qid * 2) =
                packh2(oacc[dt][2] * ri1, oacc[dt][3] * ri1);
        }
    }
}

// ---------------------------------------------------------------------------
// Launch. Inputs: 0 x, 1 mask, 2 w1, 3 b1, 4 w2, 5 b2, 6 bias_table
// ---------------------------------------------------------------------------
extern "C" void kernel_launch(void* const* d_in, const int* in_sizes, int n_in,
                              void* d_out, int out_size) {
    const float* x     = (const float*)d_in[0];
    const float* mask  = (const float*)d_in[1];
    const float* w1    = (const float*)d_in[2];
    const float* b1    = (const float*)d_in[3];
    const float* w2    = (const float*)d_in[4];
    const float* b2    = (const float*)d_in[5];
    const float* table = (const float*)d_in[6];
    float* out = (float*)d_out;

    static bool attr_done = false;
    if (!attr_done) {
        cudaFuncSetAttribute(tc_gemm_qkv,
                             cudaFuncAttributeMaxDynamicSharedMemorySize, QKV_SMEM);
        cudaFuncSetAttribute(tc_gemm_out,
                             cudaFuncAttributeMaxDynamicSharedMemorySize, OUT_SMEM);
        cudaFuncSetAttribute(attn_mma_kernel,
                             cudaFuncAttributeMaxDynamicSharedMemorySize, ATTN_SMEM);
        attr_done = true;
    }

    wsplit_kernel<<<768, 192>>>(w1, w2);
    bias_gather_kernel<<<dim3(648, 6), 256>>>(table);
    tc_gemm_qkv<<<810, 256, QKV_SMEM>>>(x, b1);
    attn_mma_kernel<<<TOW * NHEAD, 288, ATTN_SMEM>>>(mask);
    tc_gemm_out<<<810, 256, OUT_SMEM>>>(b2, out);
}

// round 15
// speedup vs baseline: 2.3883x; 1.1616x over previous
#include <cuda_runtime.h>
#include <cuda_bf16.h>
#include <cuda_fp16.h>
#include <cstdint>
#include <cstddef>

// Problem constants
#define NW    720
#define LTOK  144
#define DIM   192
#define NHEAD 6
#define HD    32
#define TOW   240
#define SCALE 0.17677669529663687f   // 32^-0.5

// ---------------------------------------------------------------------------
// Scratch
// ---------------------------------------------------------------------------
__device__ __half g_qkv[(size_t)NW * 3 * NHEAD * LTOK * HD];  // fp16 [w][t][h][l][d]
__device__ float g_bias[(size_t)TOW * NHEAD * LTOK * LTOK];   // [tow*6+h][i*144+j]
__device__ __half g_att[(size_t)NW * LTOK * DIM];             // fp16 [w][l][h*32+d]
__device__ __half g_w1h[576 * 192];                           // fp16, Q rows pre-scaled
__device__ __half g_w2h[192 * 192];                           // fp16

__device__ __forceinline__ int posidx(int a, int b) {
    int za = a / 72, ha = (a % 72) / 12, wa = a % 12;
    int zb = b / 72, hb = (b % 72) / 12, wb = b % 12;
    return 828 * (za + 2 * zb) + 23 * (ha + 6 * hb) + (wa - wb + 11);
}

__device__ __forceinline__ uint32_t smem_u32(const void* p) {
    uint32_t a;
    asm("{ .reg .u64 t; cvta.to.shared.u64 t, %1; cvt.u32.u64 %0, t; }"
        : "=r"(a) : "l"(p));
    return a;
}
__device__ __forceinline__ uint32_t packh2(float a, float b) {
    __half2 t = __floats2half2_rn(a, b);
    return *reinterpret_cast<uint32_t*>(&t);
}
__device__ __forceinline__ void ldsm4(uint32_t* r, uint32_t addr) {
    asm volatile("ldmatrix.sync.aligned.m8n8.x4.shared.b16 {%0,%1,%2,%3}, [%4];"
                 : "=r"(r[0]), "=r"(r[1]), "=r"(r[2]), "=r"(r[3]) : "r"(addr));
}
__device__ __forceinline__ void ldsm4t(uint32_t* r, uint32_t addr) {
    asm volatile("ldmatrix.sync.aligned.m8n8.x4.trans.shared.b16 {%0,%1,%2,%3}, [%4];"
                 : "=r"(r[0]), "=r"(r[1]), "=r"(r[2]), "=r"(r[3]) : "r"(addr));
}
__device__ __forceinline__ void mma16816h(float* d, const uint32_t* a, const uint32_t* b) {
    asm volatile(
        "mma.sync.aligned.m16n8k16.row.col.f32.f16.f16.f32 "
        "{%0,%1,%2,%3}, {%4,%5,%6,%7}, {%8,%9}, {%0,%1,%2,%3};"
        : "+f"(d[0]), "+f"(d[1]), "+f"(d[2]), "+f"(d[3])
        : "r"(a[0]), "r"(a[1]), "r"(a[2]), "r"(a[3]), "r"(b[0]), "r"(b[1]));
}

// FFMA-pipe exponential. rel err ~3e-8 for moderate |x|.
__device__ __forceinline__ float exp_fma(float x) {
    float t = x * 1.4426950408889634f;
    float r = rintf(t);
    float f = t - r;
    float p = 1.5423875e-4f;
    p = p * f + 1.3333558e-3f;
    p = p * f + 9.6181291e-3f;
    p = p * f + 5.5504109e-2f;
    p = p * f + 2.4022651e-1f;
    p = p * f + 6.9314718e-1f;
    p = p * f + 1.0f;
    int e = (int)r;
    float s = __int_as_float((e + 127) << 23);
    return s * p;
}

// ---------------------------------------------------------------------------
// K-1: weight prep -> fp16 (w1 Q-rows pre-scaled).
// ---------------------------------------------------------------------------
__global__ void wsplit_kernel(const float* __restrict__ w1,
                              const float* __restrict__ w2) {
    const int row = blockIdx.x, col = threadIdx.x;
    if (row < 576) {
        float v = w1[row * 192 + col];
        if (row < 192) v *= SCALE;
        g_w1h[row * 192 + col] = __float2half(v);
    } else {
        int r = row - 576;
        g_w2h[r * 192 + col] = __float2half(w2[r * 192 + col]);
    }
}

// ---------------------------------------------------------------------------
// K0: bias gather/transpose
// ---------------------------------------------------------------------------
__global__ void bias_gather_kernel(const float* __restrict__ table) {
    __shared__ float tile[32][241];
    const int ij0 = blockIdx.x * 32;
    const int tt0 = blockIdx.y * 240;
    const int tid = threadIdx.x;

    for (int e = tid; e < 32 * 240; e += 256) {
        int ii = e / 240, tt = e % 240;
        int ij = ij0 + ii;
        int a = ij / LTOK, b = ij % LTOK;
        tile[ii][tt] = table[(size_t)posidx(a, b) * (TOW * NHEAD) + tt0 + tt];
    }
    __syncthreads();
    for (int e = tid; e < 32 * 240; e += 256) {
        int tt = e / 32, c = e % 32;
        g_bias[(size_t)(tt0 + tt) * (LTOK * LTOK) + ij0 + c] = tile[c][tt];
    }
}

// ---------------------------------------------------------------------------
// K1: qkv GEMM, single-term fp16. BM=128, 256 thr (4m x 2n warps of 32x32),
// grid 810, smem 76.8KB -> 2 CTA/SM. fp16 scatter-store to g_qkv.
// ---------------------------------------------------------------------------
#define ROWB  400
#define QA_OFF 0
#define QB_OFF (128 * ROWB)                  // 51200
#define QKV_SMEM (QB_OFF + 64 * ROWB)        // 76800

__global__ __launch_bounds__(256)
void tc_gemm_qkv(const float* __restrict__ x, const float* __restrict__ bias) {
    extern __shared__ __align__(16) char sm[];
    const uint32_t smb = smem_u32(sm);
    const int tid = threadIdx.x;
    const int wid = tid >> 5, lane = tid & 31;
    const int m0 = blockIdx.x * 128;

    // A fill: 128 x 192 fp32 -> fp16
    for (int e = tid; e < 128 * 48; e += 256) {
        int m = e / 48, k4 = e % 48;
        float4 v = *reinterpret_cast<const float4*>(x + (size_t)(m0 + m) * 192 + k4 * 4);
        *reinterpret_cast<uint2*>(sm + QA_OFF + m * ROWB + k4 * 8) =
            make_uint2(packh2(v.x, v.y), packh2(v.z, v.w));
    }

    const int wm = wid & 3, wn = wid >> 2;       // 4x2 warp grid
    const int gid = lane >> 2, qid = lane & 3;
    const int g = lane >> 3, r8 = lane & 7;

    for (int nt = 0; nt < 9; nt++) {
        if (nt) __syncthreads();
        for (int e = tid; e < 64 * 24; e += 256) {
            int n = e / 24, c = e % 24;
            *reinterpret_cast<uint4*>(sm + QB_OFF + n * ROWB + c * 16) =
                *reinterpret_cast<const uint4*>(g_w1h + (size_t)(nt * 64 + n) * 192 + c * 8);
        }
        __syncthreads();

        float acc[2][4][4];
#pragma unroll
        for (int i = 0; i < 2; i++)
#pragma unroll
            for (int j = 0; j < 4; j++)
#pragma unroll
                for (int c = 0; c < 4; c++) acc[i][j][c] = 0.0f;

#pragma unroll 3
        for (int ks = 0; ks < 12; ks++) {
            const int k0 = ks * 16;
            uint32_t aa[2][4];
#pragma unroll
            for (int mt = 0; mt < 2; mt++) {
                uint32_t row = wm * 32 + mt * 16 + r8 + (g & 1) * 8;
                uint32_t koff = (k0 + (g >> 1) * 8) * 2;
                ldsm4(aa[mt], smb + QA_OFF + row * ROWB + koff);
            }
            uint32_t bb[4][2];
#pragma unroll
            for (int pr = 0; pr < 2; pr++) {
                uint32_t row = wn * 32 + pr * 16 + r8 + (g >> 1) * 8;
                uint32_t koff = (k0 + (g & 1) * 8) * 2;
                uint32_t tb[4];
                ldsm4(tb, smb + QB_OFF + row * ROWB + koff);
                bb[pr * 2 + 0][0] = tb[0]; bb[pr * 2 + 0][1] = tb[1];
                bb[pr * 2 + 1][0] = tb[2]; bb[pr * 2 + 1][1] = tb[3];
            }
#pragma unroll
            for (int mt = 0; mt < 2; mt++)
#pragma unroll
                for (int ntn = 0; ntn < 4; ntn++)
                    mma16816h(acc[mt][ntn], aa[mt], bb[ntn]);
        }

        const int cbase = nt * 64 + wn * 32;
#pragma unroll
        for (int ntn = 0; ntn < 4; ntn++) {
            const int c = cbase + ntn * 8 + qid * 2;
            float2 bv = *reinterpret_cast<const float2*>(bias + c);
            if (c < 192) { bv.x *= SCALE; bv.y *= SCALE; }
            const int t = c / DIM, hh = (c % DIM) / HD, d = c % HD;
#pragma unroll
            for (int mt = 0; mt < 2; mt++) {
#pragma unroll
                for (int half = 0; half < 2; half++) {
                    const int m = m0 + wm * 32 + mt * 16 + gid + half * 8;
                    const int w = m / LTOK, l = m % LTOK;
                    *reinterpret_cast<uint32_t*>(
                        g_qkv + ((((size_t)w * 3 + t) * NHEAD + hh) * LTOK + l) * HD + d)
                        = packh2(acc[mt][ntn][half * 2 + 0] + bv.x,
                                 acc[mt][ntn][half * 2 + 1] + bv.y);
                }
            }
        }
    }
}

// ---------------------------------------------------------------------------
// K3: out-proj GEMM, single-term fp16. BM=128, 256 thr, grid 810.
// ---------------------------------------------------------------------------
#define OA_OFF 0
#define OB_OFF (128 * ROWB)
#define OUT_SMEM (OB_OFF + 64 * ROWB)        // 76800

__global__ __launch_bounds__(256)
void tc_gemm_out(const float* __restrict__ bias, float* __restrict__ C) {
    extern __shared__ __align__(16) char sm[];
    const uint32_t smb = smem_u32(sm);
    const int tid = threadIdx.x;
    const int wid = tid >> 5, lane = tid & 31;
    const int m0 = blockIdx.x * 128;

    // A fill: pure fp16 copies (128 rows x 24 uint4)
    for (int e = tid; e < 128 * 24; e += 256) {
        int m = e / 24, c4 = e % 24;
        *reinterpret_cast<uint4*>(sm + OA_OFF + m * ROWB + c4 * 16) =
            *reinterpret_cast<const uint4*>(g_att + (size_t)(m0 + m) * 192 + c4 * 8);
    }

    const int wm = wid & 3, wn = wid >> 2;
    const int gid = lane >> 2, qid = lane & 3;
    const int g = lane >> 3, r8 = lane & 7;

    for (int nt = 0; nt < 3; nt++) {
        if (nt) __syncthreads();
        for (int e = tid; e < 64 * 24; e += 256) {
            int n = e / 24, c = e % 24;
            *reinterpret_cast<uint4*>(sm + OB_OFF + n * ROWB + c * 16) =
                *reinterpret_cast<const uint4*>(g_w2h + (size_t)(nt * 64 + n) * 192 + c * 8);
        }
        __syncthreads();

        float acc[2][4][4];
#pragma unroll
        for (int i = 0; i < 2; i++)
#pragma unroll
            for (int j = 0; j < 4; j++)
#pragma unroll
                for (int c = 0; c < 4; c++) acc[i][j][c] = 0.0f;

#pragma unroll 3
        for (int ks = 0; ks < 12; ks++) {
            const int k0 = ks * 16;
            uint32_t aa[2][4];
#pragma unroll
            for (int mt = 0; mt < 2; mt++) {
                uint32_t row = wm * 32 + mt * 16 + r8 + (g & 1) * 8;
                uint32_t koff = (k0 + (g >> 1) * 8) * 2;
                ldsm4(aa[mt], smb + OA_OFF + row * ROWB + koff);
            }
            uint32_t bb[4][2];
#pragma unroll
            for (int pr = 0; pr < 2; pr++) {
                uint32_t row = wn * 32 + pr * 16 + r8 + (g >> 1) * 8;
                uint32_t koff = (k0 + (g & 1) * 8) * 2;
                uint32_t tb[4];
                ldsm4(tb, smb + OB_OFF + row * ROWB + koff);
                bb[pr * 2 + 0][0] = tb[0]; bb[pr * 2 + 0][1] = tb[1];
                bb[pr * 2 + 1][0] = tb[2]; bb[pr * 2 + 1][1] = tb[3];
            }
#pragma unroll
            for (int mt = 0; mt < 2; mt++)
#pragma unroll
                for (int ntn = 0; ntn < 4; ntn++)
                    mma16816h(acc[mt][ntn], aa[mt], bb[ntn]);
        }

        const int cbase = nt * 64 + wn * 32;
#pragma unroll
        for (int ntn = 0; ntn < 4; ntn++) {
            const int c = cbase + ntn * 8 + qid * 2;
            const float2 bv = *reinterpret_cast<const float2*>(bias + c);
#pragma unroll
            for (int mt = 0; mt < 2; mt++) {
#pragma unroll
                for (int half = 0; half < 2; half++) {
                    const int m = m0 + wm * 32 + mt * 16 + gid + half * 8;
                    *reinterpret_cast<float2*>(C + (size_t)m * DIM + c) =
                        make_float2(acc[mt][ntn][half * 2 + 0] + bv.x,
                                    acc[mt][ntn][half * 2 + 1] + bv.y);
                }
            }
        }
    }
}

// ---------------------------------------------------------------------------
// K2: HMMA fp16 attention (R14 version, unchanged: 3 CTA/SM).
// ---------------------------------------------------------------------------
#define AROW 80
#define SQ_OFF 0
#define SK_OFF (LTOK * AROW)
#define SV_OFF (2 * LTOK * AROW)
#define SB_OFF (3 * LTOK * AROW)
#define SBSTRIDE 146
#define ATTN_SMEM (SB_OFF + LTOK * SBSTRIDE * 2)   // 76608

__global__ __launch_bounds__(288)
void attn_mma_kernel(const float* __restrict__ mask) {
    extern __shared__ __align__(16) char sm[];
    const int bx = blockIdx.x;
    const int tow = bx / NHEAD;
    const int h = bx % NHEAD;
    const int tid = threadIdx.x;
    const int warp = tid >> 5, lane = tid & 31;
    const int gid = lane >> 2, qid = lane & 3;
    const int g = lane >> 3, r8 = lane & 7;
    const uint32_t smb = smem_u32(sm);
    const int r0 = warp * 16;

    const float* bias_base = g_bias + ((size_t)tow * NHEAD + h) * (LTOK * LTOK);
    for (int e = tid; e < LTOK * 72; e += 288) {
        int row = e / 72, c2 = e % 72;
        float2 v = *reinterpret_cast<const float2*>(bias_base + row * LTOK + c2 * 2);
        *reinterpret_cast<uint32_t*>(sm + SB_OFF + (row * SBSTRIDE + c2 * 2) * 2) =
            packh2(v.x, v.y);
    }

    const __half* sb0 = reinterpret_cast<const __half*>(sm + SB_OFF) + (r0 + gid) * SBSTRIDE;
    const __half* sb1 = sb0 + 8 * SBSTRIDE;

    for (int wrep = 0; wrep < 3; wrep++) {
        const int w = tow + wrep * TOW;
        const __half* qg = g_qkv + (((size_t)w * 3 + 0) * NHEAD + h) * (LTOK * HD);
        const __half* kg = g_qkv + (((size_t)w * 3 + 1) * NHEAD + h) * (LTOK * HD);
        const __half* vg = g_qkv + (((size_t)w * 3 + 2) * NHEAD + h) * (LTOK * HD);

        __syncthreads();
        for (int e = tid; e < LTOK * 4; e += 288) {
            int row = e >> 2, c4 = e & 3;
            uint32_t off = row * AROW + c4 * 16;
            *reinterpret_cast<uint4*>(sm + SQ_OFF + off) =
                *reinterpret_cast<const uint4*>(qg + row * HD + c4 * 8);
            *reinterpret_cast<uint4*>(sm + SK_OFF + off) =
                *reinterpret_cast<const uint4*>(kg + row * HD + c4 * 8);
            *reinterpret_cast<uint4*>(sm + SV_OFF + off) =
                *reinterpret_cast<const uint4*>(vg + row * HD + c4 * 8);
        }
        __syncthreads();

        uint32_t aq[2][4];
#pragma unroll
        for (int ks = 0; ks < 2; ks++)
            ldsm4(aq[ks], smb + SQ_OFF + (r0 + r8 + (g & 1) * 8) * AROW
                              + (ks * 16 + (g >> 1) * 8) * 2);

        float oacc[4][4];
#pragma unroll
        for (int i = 0; i < 4; i++)
#pragma unroll
            for (int c = 0; c < 4; c++) oacc[i][c] = 0.0f;
        float ls0 = 0.0f, ls1 = 0.0f;

        const float* mrow0 = mask + ((size_t)w * LTOK + r0 + gid) * LTOK;
        const float* mrow1 = mrow0 + 8 * LTOK;

#pragma unroll 3
        for (int nc = 0; nc < 9; nc++) {
            float sacc[2][4] = {{0.f, 0.f, 0.f, 0.f}, {0.f, 0.f, 0.f, 0.f}};
#pragma unroll
            for (int ks = 0; ks < 2; ks++) {
                uint32_t kb[4];
                ldsm4(kb, smb + SK_OFF + (nc * 16 + r8 + (g >> 1) * 8) * AROW
                              + (ks * 16 + (g & 1) * 8) * 2);
                mma16816h(sacc[0], aq[ks], kb + 0);
                mma16816h(sacc[1], aq[ks], kb + 2);
            }
            uint32_t pa[4];
#pragma unroll
            for (int t2 = 0; t2 < 2; t2++) {
                int col = nc * 16 + t2 * 8 + qid * 2;
                float2 b0 = __half22float2(*reinterpret_cast<const __half2*>(sb0 + col));
                float2 b1 = __half22float2(*reinterpret_cast<const __half2*>(sb1 + col));
                float2 m0 = *reinterpret_cast<const float2*>(mrow0 + col);
                float2 m1 = *reinterpret_cast<const float2*>(mrow1 + col);
                float p0 = exp_fma(sacc[t2][0] + b0.x + m0.x);
                float p1 = exp_fma(sacc[t2][1] + b0.y + m0.y);
                float p2 = exp_fma(sacc[t2][2] + b1.x + m1.x);
                float p3 = exp_fma(sacc[t2][3] + b1.y + m1.y);
                ls0 += p0 + p1;
                ls1 += p2 + p3;
                pa[2 * t2 + 0] = packh2(p0, p1);
                pa[2 * t2 + 1] = packh2(p2, p3);
            }
#pragma unroll
            for (int dh = 0; dh < 2; dh++) {
                uint32_t vb[4];
                ldsm4t(vb, smb + SV_OFF + (nc * 16 + (g & 1) * 8 + r8) * AROW
                               + (dh * 16 + (g >> 1) * 8) * 2);
                mma16816h(oacc[dh * 2 + 0], pa, vb + 0);
                mma16816h(oacc[dh * 2 + 1], pa, vb + 2);
            }
        }

        ls0 += __shfl_xor_sync(0xFFFFFFFFu, ls0, 1);
        ls0 += __shfl_xor_sync(0xFFFFFFFFu, ls0, 2);
        ls1 += __shfl_xor_sync(0xFFFFFFFFu, ls1, 1);
        ls1 += __shfl_xor_sync(0xFFFFFFFFu, ls1, 2);
        const float ri0 = 1.0f / ls0;
        const float ri1 = 1.0f / ls1;

        __half* ob0 = g_att + ((size_t)w * LTOK + r0 + gid) * DIM + h * HD;
        __half* ob1 = ob0 + 8 * DIM;
#pragma unroll
        for (int dt = 0; dt < 4; dt++) {
            *reinterpret_cast<uint32_t*>(ob0 + dt * 8 + qid * 2) =
                packh2(oacc[dt][0] * ri0, oacc[dt][1] * ri0);
            *reinterpret_cast<uint32_t*>(ob1 + dt * 8 + qid * 2) =
                packh2(oacc[dt][2] * ri1, oacc[dt][3] * ri1);
        }
    }
}

// ---------------------------------------------------------------------------
// Launch. Inputs: 0 x, 1 mask, 2 w1, 3 b1, 4 w2, 5 b2, 6 bias_table
// ---------------------------------------------------------------------------
extern "C" void kernel_launch(void* const* d_in, const int* in_sizes, int n_in,
                              void* d_out, int out_size) {
    const float* x     = (const float*)d_in[0];
    const float* mask  = (const float*)d_in[1];
    const float* w1    = (const float*)d_in[2];
    const float* b1    = (const float*)d_in[3];
    const float* w2    = (const float*)d_in[4];
    const float* b2    = (const float*)d_in[5];
    const float* table = (const float*)d_in[6];
    float* out = (float*)d_out;

    static bool attr_done = false;
    if (!attr_done) {
        cudaFuncSetAttribute(tc_gemm_qkv,
                             cudaFuncAttributeMaxDynamicSharedMemorySize, QKV_SMEM);
        cudaFuncSetAttribute(tc_gemm_out,
                             cudaFuncAttributeMaxDynamicSharedMemorySize, OUT_SMEM);
        cudaFuncSetAttribute(attn_mma_kernel,
                             cudaFuncAttributeMaxDynamicSharedMemorySize, ATTN_SMEM);
        attr_done = true;
    }

    wsplit_kernel<<<768, 192>>>(w1, w2);
    bias_gather_kernel<<<dim3(648, 6), 256>>>(table);
    tc_gemm_qkv<<<810, 256, QKV_SMEM>>>(x, b1);
    attn_mma_kernel<<<TOW * NHEAD, 288, ATTN_SMEM>>>(mask);
    tc_gemm_out<<<810, 256, OUT_SMEM>>>(b2, out);
}

// round 16
// speedup vs baseline: 2.4854x; 1.0407x over previous
#include <cuda_runtime.h>
#include <cuda_bf16.h>
#include <cuda_fp16.h>
#include <cstdint>
#include <cstddef>

// Problem constants
#define NW    720
#define LTOK  144
#define DIM   192
#define NHEAD 6
#define HD    32
#define TOW   240
#define SCALE 0.17677669529663687f   // 32^-0.5

// ---------------------------------------------------------------------------
// Scratch
// ---------------------------------------------------------------------------
__device__ __half g_qkv[(size_t)NW * 3 * NHEAD * LTOK * HD];  // fp16 [w][t][h][l][d]
__device__ float g_bias[(size_t)TOW * NHEAD * LTOK * LTOK];   // [tow*6+h][i*144+j]
__device__ __half g_att[(size_t)NW * LTOK * DIM];             // fp16 [w][l][h*32+d]
__device__ __half g_w1h[576 * 192];                           // fp16, Q rows pre-scaled
__device__ __half g_w2h[192 * 192];                           // fp16

__device__ __forceinline__ int posidx(int a, int b) {
    int za = a / 72, ha = (a % 72) / 12, wa = a % 12;
    int zb = b / 72, hb = (b % 72) / 12, wb = b % 12;
    return 828 * (za + 2 * zb) + 23 * (ha + 6 * hb) + (wa - wb + 11);
}

__device__ __forceinline__ uint32_t smem_u32(const void* p) {
    uint32_t a;
    asm("{ .reg .u64 t; cvta.to.shared.u64 t, %1; cvt.u32.u64 %0, t; }"
        : "=r"(a) : "l"(p));
    return a;
}
__device__ __forceinline__ uint32_t packh2(float a, float b) {
    __half2 t = __floats2half2_rn(a, b);
    return *reinterpret_cast<uint32_t*>(&t);
}
__device__ __forceinline__ void ldsm4(uint32_t* r, uint32_t addr) {
    asm volatile("ldmatrix.sync.aligned.m8n8.x4.shared.b16 {%0,%1,%2,%3}, [%4];"
                 : "=r"(r[0]), "=r"(r[1]), "=r"(r[2]), "=r"(r[3]) : "r"(addr));
}
__device__ __forceinline__ void ldsm4t(uint32_t* r, uint32_t addr) {
    asm volatile("ldmatrix.sync.aligned.m8n8.x4.trans.shared.b16 {%0,%1,%2,%3}, [%4];"
                 : "=r"(r[0]), "=r"(r[1]), "=r"(r[2]), "=r"(r[3]) : "r"(addr));
}
__device__ __forceinline__ void mma16816h(float* d, const uint32_t* a, const uint32_t* b) {
    asm volatile(
        "mma.sync.aligned.m16n8k16.row.col.f32.f16.f16.f32 "
        "{%0,%1,%2,%3}, {%4,%5,%6,%7}, {%8,%9}, {%0,%1,%2,%3};"
        : "+f"(d[0]), "+f"(d[1]), "+f"(d[2]), "+f"(d[3])
        : "r"(a[0]), "r"(a[1]), "r"(a[2]), "r"(a[3]), "r"(b[0]), "r"(b[1]));
}

// FFMA-pipe exponential. rel err ~3e-8 for moderate |x|.
__device__ __forceinline__ float exp_fma(float x) {
    float t = x * 1.4426950408889634f;
    float r = rintf(t);
    float f = t - r;
    float p = 1.5423875e-4f;
    p = p * f + 1.3333558e-3f;
    p = p * f + 9.6181291e-3f;
    p = p * f + 5.5504109e-2f;
    p = p * f + 2.4022651e-1f;
    p = p * f + 6.9314718e-1f;
    p = p * f + 1.0f;
    int e = (int)r;
    float s = __int_as_float((e + 127) << 23);
    return s * p;
}

// ---------------------------------------------------------------------------
// K-1: weight prep -> fp16 (w1 Q-rows pre-scaled).
// ---------------------------------------------------------------------------
__global__ void wsplit_kernel(const float* __restrict__ w1,
                              const float* __restrict__ w2) {
    const int row = blockIdx.x, col = threadIdx.x;
    if (row < 576) {
        float v = w1[row * 192 + col];
        if (row < 192) v *= SCALE;
        g_w1h[row * 192 + col] = __float2half(v);
    } else {
        int r = row - 576;
        g_w2h[r * 192 + col] = __float2half(w2[r * 192 + col]);
    }
}

// ---------------------------------------------------------------------------
// K0: bias gather/transpose
// ---------------------------------------------------------------------------
__global__ void bias_gather_kernel(const float* __restrict__ table) {
    __shared__ float tile[32][241];
    const int ij0 = blockIdx.x * 32;
    const int tt0 = blockIdx.y * 240;
    const int tid = threadIdx.x;

    for (int e = tid; e < 32 * 240; e += 256) {
        int ii = e / 240, tt = e % 240;
        int ij = ij0 + ii;
        int a = ij / LTOK, b = ij % LTOK;
        tile[ii][tt] = table[(size_t)posidx(a, b) * (TOW * NHEAD) + tt0 + tt];
    }
    __syncthreads();
    for (int e = tid; e < 32 * 240; e += 256) {
        int tt = e / 32, c = e % 32;
        g_bias[(size_t)(tt0 + tt) * (LTOK * LTOK) + ij0 + c] = tile[c][tt];
    }
}

// ---------------------------------------------------------------------------
// K1: qkv GEMM, single-term fp16. BM=128, 256 thr (4m x 2n warps of 32x32),
// grid 810, smem 76.8KB -> 2 CTA/SM. fp16 scatter-store to g_qkv.
// Epilogue addresses: precomputed row bases + column offsets (no div/mod in
// the store loop).
// ---------------------------------------------------------------------------
#define ROWB  400
#define QA_OFF 0
#define QB_OFF (128 * ROWB)                  // 51200
#define QKV_SMEM (QB_OFF + 64 * ROWB)        // 76800

__global__ __launch_bounds__(256)
void tc_gemm_qkv(const float* __restrict__ x, const float* __restrict__ bias) {
    extern __shared__ __align__(16) char sm[];
    const uint32_t smb = smem_u32(sm);
    const int tid = threadIdx.x;
    const int wid = tid >> 5, lane = tid & 31;
    const int m0 = blockIdx.x * 128;

    // A fill: 128 x 192 fp32 -> fp16
    for (int e = tid; e < 128 * 48; e += 256) {
        int m = e / 48, k4 = e % 48;
        float4 v = *reinterpret_cast<const float4*>(x + (size_t)(m0 + m) * 192 + k4 * 4);
        *reinterpret_cast<uint2*>(sm + QA_OFF + m * ROWB + k4 * 8) =
            make_uint2(packh2(v.x, v.y), packh2(v.z, v.w));
    }

    const int wm = wid & 3, wn = wid >> 2;       // 4x2 warp grid
    const int gid = lane >> 2, qid = lane & 3;
    const int g = lane >> 3, r8 = lane & 7;

    // Precompute per-(mt,half) row bases: w*82944 + l*32
    size_t rowbase[2][2];
#pragma unroll
    for (int mt = 0; mt < 2; mt++)
#pragma unroll
        for (int half = 0; half < 2; half++) {
            const int m = m0 + wm * 32 + mt * 16 + gid + half * 8;
            const int w = m / LTOK, l = m % LTOK;
            rowbase[mt][half] = (size_t)w * (3 * NHEAD * LTOK * HD) + l * HD;
        }

    for (int nt = 0; nt < 9; nt++) {
        if (nt) __syncthreads();
        for (int e = tid; e < 64 * 24; e += 256) {
            int n = e / 24, c = e % 24;
            *reinterpret_cast<uint4*>(sm + QB_OFF + n * ROWB + c * 16) =
                *reinterpret_cast<const uint4*>(g_w1h + (size_t)(nt * 64 + n) * 192 + c * 8);
        }
        __syncthreads();

        float acc[2][4][4];
#pragma unroll
        for (int i = 0; i < 2; i++)
#pragma unroll
            for (int j = 0; j < 4; j++)
#pragma unroll
                for (int c = 0; c < 4; c++) acc[i][j][c] = 0.0f;

#pragma unroll 3
        for (int ks = 0; ks < 12; ks++) {
            const int k0 = ks * 16;
            uint32_t aa[2][4];
#pragma unroll
            for (int mt = 0; mt < 2; mt++) {
                uint32_t row = wm * 32 + mt * 16 + r8 + (g & 1) * 8;
                uint32_t koff = (k0 + (g >> 1) * 8) * 2;
                ldsm4(aa[mt], smb + QA_OFF + row * ROWB + koff);
            }
            uint32_t bb[4][2];
#pragma unroll
            for (int pr = 0; pr < 2; pr++) {
                uint32_t row = wn * 32 + pr * 16 + r8 + (g >> 1) * 8;
                uint32_t koff = (k0 + (g & 1) * 8) * 2;
                uint32_t tb[4];
                ldsm4(tb, smb + QB_OFF + row * ROWB + koff);
                bb[pr * 2 + 0][0] = tb[0]; bb[pr * 2 + 0][1] = tb[1];
                bb[pr * 2 + 1][0] = tb[2]; bb[pr * 2 + 1][1] = tb[3];
            }
#pragma unroll
            for (int mt = 0; mt < 2; mt++)
#pragma unroll
                for (int ntn = 0; ntn < 4; ntn++)
                    mma16816h(acc[mt][ntn], aa[mt], bb[ntn]);
        }

        const int cbase = nt * 64 + wn * 32;
#pragma unroll
        for (int ntn = 0; ntn < 4; ntn++) {
            const int c = cbase + ntn * 8 + qid * 2;
            float2 bv = *reinterpret_cast<const float2*>(bias + c);
            if (c < 192) { bv.x *= SCALE; bv.y *= SCALE; }
            const int t = c / DIM, hh = (c % DIM) / HD, d = c % HD;
            const size_t coff = (size_t)t * (NHEAD * LTOK * HD) + hh * (LTOK * HD) + d;
#pragma unroll
            for (int mt = 0; mt < 2; mt++) {
#pragma unroll
                for (int half = 0; half < 2; half++) {
                    *reinterpret_cast<uint32_t*>(g_qkv + rowbase[mt][half] + coff)
                        = packh2(acc[mt][ntn][half * 2 + 0] + bv.x,
                                 acc[mt][ntn][half * 2 + 1] + bv.y);
                }
            }
        }
    }
}

// ---------------------------------------------------------------------------
// K3: out-proj GEMM, single-term fp16. BM=128, 256 thr, grid 810.
// ---------------------------------------------------------------------------
#define OA_OFF 0
#define OB_OFF (128 * ROWB)
#define OUT_SMEM (OB_OFF + 64 * ROWB)        // 76800

__global__ __launch_bounds__(256)
void tc_gemm_out(const float* __restrict__ bias, float* __restrict__ C) {
    extern __shared__ __align__(16) char sm[];
    const uint32_t smb = smem_u32(sm);
    const int tid = threadIdx.x;
    const int wid = tid >> 5, lane = tid & 31;
    const int m0 = blockIdx.x * 128;

    for (int e = tid; e < 128 * 24; e += 256) {
        int m = e / 24, c4 = e % 24;
        *reinterpret_cast<uint4*>(sm + OA_OFF + m * ROWB + c4 * 16) =
            *reinterpret_cast<const uint4*>(g_att + (size_t)(m0 + m) * 192 + c4 * 8);
    }

    const int wm = wid & 3, wn = wid >> 2;
    const int gid = lane >> 2, qid = lane & 3;
    const int g = lane >> 3, r8 = lane & 7;

    for (int nt = 0; nt < 3; nt++) {
        if (nt) __syncthreads();
        for (int e = tid; e < 64 * 24; e += 256) {
            int n = e / 24, c = e % 24;
            *reinterpret_cast<uint4*>(sm + OB_OFF + n * ROWB + c * 16) =
                *reinterpret_cast<const uint4*>(g_w2h + (size_t)(nt * 64 + n) * 192 + c * 8);
        }
        __syncthreads();

        float acc[2][4][4];
#pragma unroll
        for (int i = 0; i < 2; i++)
#pragma unroll
            for (int j = 0; j < 4; j++)
#pragma unroll
                for (int c = 0; c < 4; c++) acc[i][j][c] = 0.0f;

#pragma unroll 3
        for (int ks = 0; ks < 12; ks++) {
            const int k0 = ks * 16;
            uint32_t aa[2][4];
#pragma unroll
            for (int mt = 0; mt < 2; mt++) {
                uint32_t row = wm * 32 + mt * 16 + r8 + (g & 1) * 8;
                uint32_t koff = (k0 + (g >> 1) * 8) * 2;
                ldsm4(aa[mt], smb + OA_OFF + row * ROWB + koff);
            }
            uint32_t bb[4][2];
#pragma unroll
            for (int pr = 0; pr < 2; pr++) {
                uint32_t row = wn * 32 + pr * 16 + r8 + (g >> 1) * 8;
                uint32_t koff = (k0 + (g & 1) * 8) * 2;
                uint32_t tb[4];
                ldsm4(tb, smb + OB_OFF + row * ROWB + koff);
                bb[pr * 2 + 0][0] = tb[0]; bb[pr * 2 + 0][1] = tb[1];
                bb[pr * 2 + 1][0] = tb[2]; bb[pr * 2 + 1][1] = tb[3];
            }
#pragma unroll
            for (int mt = 0; mt < 2; mt++)
#pragma unroll
                for (int ntn = 0; ntn < 4; ntn++)
                    mma16816h(acc[mt][ntn], aa[mt], bb[ntn]);
        }

        const int cbase = nt * 64 + wn * 32;
#pragma unroll
        for (int ntn = 0; ntn < 4; ntn++) {
            const int c = cbase + ntn * 8 + qid * 2;
            const float2 bv = *reinterpret_cast<const float2*>(bias + c);
#pragma unroll
            for (int mt = 0; mt < 2; mt++) {
#pragma unroll
                for (int half = 0; half < 2; half++) {
                    const int m = m0 + wm * 32 + mt * 16 + gid + half * 8;
                    *reinterpret_cast<float2*>(C + (size_t)m * DIM + c) =
                        make_float2(acc[mt][ntn][half * 2 + 0] + bv.x,
                                    acc[mt][ntn][half * 2 + 1] + bv.y);
                }
            }
        }
    }
}

// ---------------------------------------------------------------------------
// K2: HMMA fp16 attention with software-pipelined mask loads.
// Mask float2 loads for iteration nc+1 are issued before the S-mma of nc,
// covering their latency with ~2 mma + the exp chain.
// ---------------------------------------------------------------------------
#define AROW 80
#define SQ_OFF 0
#define SK_OFF (LTOK * AROW)
#define SV_OFF (2 * LTOK * AROW)
#define SB_OFF (3 * LTOK * AROW)
#define SBSTRIDE 146
#define ATTN_SMEM (SB_OFF + LTOK * SBSTRIDE * 2)   // 76608

__global__ __launch_bounds__(288)
void attn_mma_kernel(const float* __restrict__ mask) {
    extern __shared__ __align__(16) char sm[];
    const int bx = blockIdx.x;
    const int tow = bx / NHEAD;
    const int h = bx % NHEAD;
    const int tid = threadIdx.x;
    const int warp = tid >> 5, lane = tid & 31;
    const int gid = lane >> 2, qid = lane & 3;
    const int g = lane >> 3, r8 = lane & 7;
    const uint32_t smb = smem_u32(sm);
    const int r0 = warp * 16;

    const float* bias_base = g_bias + ((size_t)tow * NHEAD + h) * (LTOK * LTOK);
    for (int e = tid; e < LTOK * 72; e += 288) {
        int row = e / 72, c2 = e % 72;
        float2 v = *reinterpret_cast<const float2*>(bias_base + row * LTOK + c2 * 2);
        *reinterpret_cast<uint32_t*>(sm + SB_OFF + (row * SBSTRIDE + c2 * 2) * 2) =
            packh2(v.x, v.y);
    }

    const __half* sb0 = reinterpret_cast<const __half*>(sm + SB_OFF) + (r0 + gid) * SBSTRIDE;
    const __half* sb1 = sb0 + 8 * SBSTRIDE;

    for (int wrep = 0; wrep < 3; wrep++) {
        const int w = tow + wrep * TOW;
        const __half* qg = g_qkv + (((size_t)w * 3 + 0) * NHEAD + h) * (LTOK * HD);
        const __half* kg = g_qkv + (((size_t)w * 3 + 1) * NHEAD + h) * (LTOK * HD);
        const __half* vg = g_qkv + (((size_t)w * 3 + 2) * NHEAD + h) * (LTOK * HD);

        __syncthreads();
        for (int e = tid; e < LTOK * 4; e += 288) {
            int row = e >> 2, c4 = e & 3;
            uint32_t off = row * AROW + c4 * 16;
            *reinterpret_cast<uint4*>(sm + SQ_OFF + off) =
                *reinterpret_cast<const uint4*>(qg + row * HD + c4 * 8);
            *reinterpret_cast<uint4*>(sm + SK_OFF + off) =
                *reinterpret_cast<const uint4*>(kg + row * HD + c4 * 8);
            *reinterpret_cast<uint4*>(sm + SV_OFF + off) =
                *reinterpret_cast<const uint4*>(vg + row * HD + c4 * 8);
        }
        __syncthreads();

        uint32_t aq[2][4];
#pragma unroll
        for (int ks = 0; ks < 2; ks++)
            ldsm4(aq[ks], smb + SQ_OFF + (r0 + r8 + (g & 1) * 8) * AROW
                              + (ks * 16 + (g >> 1) * 8) * 2);

        float oacc[4][4];
#pragma unroll
        for (int i = 0; i < 4; i++)
#pragma unroll
            for (int c = 0; c < 4; c++) oacc[i][c] = 0.0f;
        float ls0 = 0.0f, ls1 = 0.0f;

        const float* mrow0 = mask + ((size_t)w * LTOK + r0 + gid) * LTOK + qid * 2;
        const float* mrow1 = mrow0 + 8 * LTOK;

        // prefetch mask for nc=0: [t2=0 row0, t2=1 row0, t2=0 row1, t2=1 row1]
        float2 pm[4];
        pm[0] = *reinterpret_cast<const float2*>(mrow0);
        pm[1] = *reinterpret_cast<const float2*>(mrow0 + 8);
        pm[2] = *reinterpret_cast<const float2*>(mrow1);
        pm[3] = *reinterpret_cast<const float2*>(mrow1 + 8);

#pragma unroll 3
        for (int nc = 0; nc < 9; nc++) {
            float2 cm0 = pm[0], cm1 = pm[1], cm2 = pm[2], cm3 = pm[3];
            if (nc < 8) {
                const int ncol = (nc + 1) * 16;
                pm[0] = *reinterpret_cast<const float2*>(mrow0 + ncol);
                pm[1] = *reinterpret_cast<const float2*>(mrow0 + ncol + 8);
                pm[2] = *reinterpret_cast<const float2*>(mrow1 + ncol);
                pm[3] = *reinterpret_cast<const float2*>(mrow1 + ncol + 8);
            }

            float sacc[2][4] = {{0.f, 0.f, 0.f, 0.f}, {0.f, 0.f, 0.f, 0.f}};
#pragma unroll
            for (int ks = 0; ks < 2; ks++) {
                uint32_t kb[4];
                ldsm4(kb, smb + SK_OFF + (nc * 16 + r8 + (g >> 1) * 8) * AROW
                              + (ks * 16 + (g & 1) * 8) * 2);
                mma16816h(sacc[0], aq[ks], kb + 0);
                mma16816h(sacc[1], aq[ks], kb + 2);
            }

            uint32_t pa[4];
            {
                int col0 = nc * 16 + qid * 2;
                float2 b00 = __half22float2(*reinterpret_cast<const __half2*>(sb0 + col0));
                float2 b01 = __half22float2(*reinterpret_cast<const __half2*>(sb0 + col0 + 8));
                float2 b10 = __half22float2(*reinterpret_cast<const __half2*>(sb1 + col0));
                float2 b11 = __half22float2(*reinterpret_cast<const __half2*>(sb1 + col0 + 8));
                float p0 = exp_fma(sacc[0][0] + b00.x + cm0.x);
                float p1 = exp_fma(sacc[0][1] + b00.y + cm0.y);
                float p2 = exp_fma(sacc[0][2] + b10.x + cm2.x);
                float p3 = exp_fma(sacc[0][3] + b10.y + cm2.y);
                float p4 = exp_fma(sacc[1][0] + b01.x + cm1.x);
                float p5 = exp_fma(sacc[1][1] + b01.y + cm1.y);
                float p6 = exp_fma(sacc[1][2] + b11.x + cm3.x);
                float p7 = exp_fma(sacc[1][3] + b11.y + cm3.y);
                ls0 += p0 + p1 + p4 + p5;
                ls1 += p2 + p3 + p6 + p7;
                pa[0] = packh2(p0, p1);
                pa[1] = packh2(p2, p3);
                pa[2] = packh2(p4, p5);
                pa[3] = packh2(p6, p7);
            }
#pragma unroll
            for (int dh = 0; dh < 2; dh++) {
                uint32_t vb[4];
                ldsm4t(vb, smb + SV_OFF + (nc * 16 + (g & 1) * 8 + r8) * AROW
                               + (dh * 16 + (g >> 1) * 8) * 2);
                mma16816h(oacc[dh * 2 + 0], pa, vb + 0);
                mma16816h(oacc[dh * 2 + 1], pa, vb + 2);
            }
        }

        ls0 += __shfl_xor_sync(0xFFFFFFFFu, ls0, 1);
        ls0 += __shfl_xor_sync(0xFFFFFFFFu, ls0, 2);
        ls1 += __shfl_xor_sync(0xFFFFFFFFu, ls1, 1);
        ls1 += __shfl_xor_sync(0xFFFFFFFFu, ls1, 2);
        const float ri0 = 1.0f / ls0;
        const float ri1 = 1.0f / ls1;

        __half* ob0 = g_att + ((size_t)w * LTOK + r0 + gid) * DIM + h * HD;
        __half* ob1 = ob0 + 8 * DIM;
#pragma unroll
        for (int dt = 0; dt < 4; dt++) {
            *reinterpret_cast<uint32_t*>(ob0 + dt * 8 + qid * 2) =
                packh2(oacc[dt][0] * ri0, oacc[dt][1] * ri0);
            *reinterpret_cast<uint32_t*>(ob1 + dt * 8 + qid * 2) =
                packh2(oacc[dt][2] * ri1, oacc[dt][3] * ri1);
        }
    }
}

// ---------------------------------------------------------------------------
// Launch. Inputs: 0 x, 1 mask, 2 w1, 3 b1, 4 w2, 5 b2, 6 bias_table
// ---------------------------------------------------------------------------
extern "C" void kernel_launch(void* const* d_in, const int* in_sizes, int n_in,
                              void* d_out, int out_size) {
    const float* x     = (const float*)d_in[0];
    const float* mask  = (const float*)d_in[1];
    const float* w1    = (const float*)d_in[2];
    const float* b1    = (const float*)d_in[3];
    const float* w2    = (const float*)d_in[4];
    const float* b2    = (const float*)d_in[5];
    const float* table = (const float*)d_in[6];
    float* out = (float*)d_out;

    static bool attr_done = false;
    if (!attr_done) {
        cudaFuncSetAttribute(tc_gemm_qkv,
                             cudaFuncAttributeMaxDynamicSharedMemorySize, QKV_SMEM);
        cudaFuncSetAttribute(tc_gemm_out,
                             cudaFuncAttributeMaxDynamicSharedMemorySize, OUT_SMEM);
        cudaFuncSetAttribute(attn_mma_kernel,
                             cudaFuncAttributeMaxDynamicSharedMemorySize, ATTN_SMEM);
        attr_done = true;
    }

    wsplit_kernel<<<768, 192>>>(w1, w2);
    bias_gather_kernel<<<dim3(648, 6), 256>>>(table);
    tc_gemm_qkv<<<810, 256, QKV_SMEM>>>(x, b1);
    attn_mma_kernel<<<TOW * NHEAD, 288, ATTN_SMEM>>>(mask);
    tc_gemm_out<<<810, 256, OUT_SMEM>>>(b2, out);
}